// round 10
// baseline (speedup 1.0000x reference)
#include <cuda_runtime.h>
#include <cuda_bf16.h>
#include <cstdint>

#define EMBED 768
#define HEADS 12
#define DKK   64
#define RDIM  128
#define CDIM  256
#define NTOK  (RDIM * CDIM)   // 32768

typedef __nv_bfloat16 bf16;
typedef __nv_bfloat162 bf162;

__device__ bf16 g_xhi[(size_t)NTOK * EMBED];
__device__ bf16 g_xlo[(size_t)NTOK * EMBED];
__device__ bf16 g_qhi[(size_t)NTOK * EMBED];
__device__ bf16 g_qlo[(size_t)NTOK * EMBED];
__device__ bf16 g_khi[(size_t)NTOK * EMBED];
__device__ bf16 g_klo[(size_t)NTOK * EMBED];
__device__ bf16 g_vhi[(size_t)NTOK * EMBED];
__device__ bf16 g_vlo[(size_t)NTOK * EMBED];
__device__ bf16 g_whi[4 * (size_t)EMBED * EMBED];
__device__ bf16 g_wlo[4 * (size_t)EMBED * EMBED];

__device__ __forceinline__ uint32_t smem_u32(const void* p) {
    uint32_t a;
    asm("{ .reg .u64 t; cvta.to.shared.u64 t, %1; cvt.u32.u64 %0, t; }"
        : "=r"(a) : "l"(p));
    return a;
}

__device__ __forceinline__ void ldsm4(uint32_t (&r)[4], uint32_t addr) {
    asm volatile("ldmatrix.sync.aligned.m8n8.x4.shared.b16 {%0,%1,%2,%3}, [%4];"
                 : "=r"(r[0]), "=r"(r[1]), "=r"(r[2]), "=r"(r[3]) : "r"(addr));
}

__device__ __forceinline__ void ldsm4t(uint32_t (&r)[4], uint32_t addr) {
    asm volatile("ldmatrix.sync.aligned.m8n8.x4.trans.shared.b16 {%0,%1,%2,%3}, [%4];"
                 : "=r"(r[0]), "=r"(r[1]), "=r"(r[2]), "=r"(r[3]) : "r"(addr));
}

__device__ __forceinline__ void mma16816(float (&c)[4], const uint32_t (&a)[4],
                                         uint32_t b0, uint32_t b1) {
    asm volatile(
        "mma.sync.aligned.m16n8k16.row.col.f32.bf16.bf16.f32 "
        "{%0,%1,%2,%3}, {%4,%5,%6,%7}, {%8,%9}, {%0,%1,%2,%3};"
        : "+f"(c[0]), "+f"(c[1]), "+f"(c[2]), "+f"(c[3])
        : "r"(a[0]), "r"(a[1]), "r"(a[2]), "r"(a[3]), "r"(b0), "r"(b1));
}

#define CP_ASYNC16(dst, src) \
    asm volatile("cp.async.cg.shared.global [%0], [%1], 16;" \
                 :: "r"(dst), "l"(src))
#define CP_COMMIT() asm volatile("cp.async.commit_group;" ::: "memory")
#define CP_WAIT0()  asm volatile("cp.async.wait_group 0;" ::: "memory")

// ---------------------------------------------------------------------------
__device__ __forceinline__ void split4(const float4 v, bf162* hp, bf162* lp) {
    bf16 h0 = __float2bfloat16(v.x);
    bf16 h1 = __float2bfloat16(v.y);
    bf16 h2 = __float2bfloat16(v.z);
    bf16 h3 = __float2bfloat16(v.w);
    bf16 l0 = __float2bfloat16(v.x - __bfloat162float(h0));
    bf16 l1 = __float2bfloat16(v.y - __bfloat162float(h1));
    bf16 l2 = __float2bfloat16(v.z - __bfloat162float(h2));
    bf16 l3 = __float2bfloat16(v.w - __bfloat162float(h3));
    hp[0] = bf162(h0, h1);
    hp[1] = bf162(h2, h3);
    lp[0] = bf162(l0, l1);
    lp[1] = bf162(l2, l3);
}

__global__ __launch_bounds__(256) void split_kernel(
    const float4* __restrict__ src, bf16* __restrict__ hi,
    bf16* __restrict__ lo, int n4)
{
    int i = blockIdx.x * blockDim.x + threadIdx.x;
    if (i >= n4) return;
    split4(src[i], (bf162*)(hi + (size_t)i * 4), (bf162*)(lo + (size_t)i * 4));
}

__global__ __launch_bounds__(256) void split_w_kernel(
    const float4* __restrict__ w0, const float4* __restrict__ w1,
    const float4* __restrict__ w2, const float4* __restrict__ w3,
    bf16* __restrict__ hi, bf16* __restrict__ lo, int n4)
{
    int i = blockIdx.x * blockDim.x + threadIdx.x;
    if (i >= n4) return;
    const float4* src = (blockIdx.y == 0) ? w0 : (blockIdx.y == 1) ? w1 :
                        (blockIdx.y == 2) ? w2 : w3;
    size_t o = (size_t)blockIdx.y * n4 * 4 + (size_t)i * 4;
    split4(src[i], (bf162*)(hi + o), (bf162*)(lo + o));
}

// ---------------------------------------------------------------------------
// mma.sync split-bf16 GEMM mainloop. CTA tile 256x128, 512 threads (16 warps,
// warp tile 64x32). K-chunk 32, cp.async 2-stage smem.
// Stage layout (bytes): Ahi 0 (256x80), Alo 20480, Bhi 40960 (128x80), Blo 51200.
// ---------------------------------------------------------------------------
#define KC      32
#define NCH     (EMBED / KC)          // 24
#define ROWB    80
#define A_TILEB (256 * ROWB)          // 20480
#define B_TILEB (128 * ROWB)          // 10240
#define STAGEB  (2 * A_TILEB + 2 * B_TILEB)   // 61440
#define GSMEM   (2 * STAGEB)          // 122880

__device__ __forceinline__ void gemm_mainloop(
    const bf16* __restrict__ Ahi, const bf16* __restrict__ Alo,
    const bf16* __restrict__ Bhi, const bf16* __restrict__ Blo,
    int row0, int col0, uint32_t sbase, float (&acc)[4][4][4])
{
    const int tid  = threadIdx.x;
    const int wid  = tid >> 5;
    const int lane = tid & 31;
    const int wm   = wid >> 2;            // 0..3: 64-row slice of 256
    const int wn   = wid & 3;             // 0..3: 32-col slice of 128

    const uint32_t a_off = (uint32_t)((lane & 15) * ROWB + (lane >> 4) * 16);
    const uint32_t b_off = (uint32_t)((((lane & 16) >> 1) + (lane & 7)) * ROWB +
                                      (((lane >> 3) & 1) * 16));

    auto load_stage = [&](int s, int c) {
        uint32_t stage = sbase + s * STAGEB;
        #pragma unroll
        for (int it = 0; it < 6; it++) {
            int u = tid + it * 512;          // 0..3071 (16B units)
            const bf16* src;
            int grow, g;
            uint32_t doff;
            if (u < 2048) {                  // A tiles: 1024 units each
                int t = u >> 10;
                int rem = u & 1023;
                int r = rem >> 2;
                g = rem & 3;
                src = t ? Alo : Ahi;
                grow = row0 + r;
                doff = (uint32_t)(t * A_TILEB + r * ROWB + g * 16);
            } else {                         // B tiles: 512 units each
                int v = u - 2048;
                int t = v >> 9;
                int rem = v & 511;
                int r = rem >> 2;
                g = rem & 3;
                src = t ? Blo : Bhi;
                grow = col0 + r;
                doff = (uint32_t)(2 * A_TILEB + t * B_TILEB + r * ROWB + g * 16);
            }
            CP_ASYNC16(stage + doff, src + (size_t)grow * EMBED + c * KC + g * 8);
        }
    };

    load_stage(0, 0);
    CP_COMMIT();

    for (int c = 0; c < NCH; c++) {
        const int s = c & 1;
        CP_WAIT0();
        __syncthreads();
        if (c + 1 < NCH) { load_stage(s ^ 1, c + 1); CP_COMMIT(); }

        const uint32_t st = sbase + s * STAGEB;
        #pragma unroll
        for (int ks = 0; ks < 2; ks++) {
            const uint32_t kb = (uint32_t)(ks * 32);
            uint32_t ah[4][4], al[4][4];
            uint32_t bh[4][2], bl[4][2];
            #pragma unroll
            for (int mt = 0; mt < 4; mt++) {
                uint32_t ra = st + (uint32_t)((wm * 64 + mt * 16) * ROWB) + kb + a_off;
                ldsm4(ah[mt], ra);
                ldsm4(al[mt], ra + A_TILEB);
            }
            #pragma unroll
            for (int np = 0; np < 2; np++) {
                uint32_t rb = st + 2 * A_TILEB +
                              (uint32_t)((wn * 32 + np * 16) * ROWB) + kb + b_off;
                uint32_t rh[4], rl[4];
                ldsm4(rh, rb);
                ldsm4(rl, rb + B_TILEB);
                bh[2 * np][0] = rh[0]; bh[2 * np][1] = rh[1];
                bh[2 * np + 1][0] = rh[2]; bh[2 * np + 1][1] = rh[3];
                bl[2 * np][0] = rl[0]; bl[2 * np][1] = rl[1];
                bl[2 * np + 1][0] = rl[2]; bl[2 * np + 1][1] = rl[3];
            }
            #pragma unroll
            for (int mt = 0; mt < 4; mt++)
                #pragma unroll
                for (int nt = 0; nt < 4; nt++) {
                    mma16816(acc[mt][nt], ah[mt], bh[nt][0], bh[nt][1]);
                    mma16816(acc[mt][nt], ah[mt], bl[nt][0], bl[nt][1]);
                    mma16816(acc[mt][nt], al[mt], bh[nt][0], bh[nt][1]);
                }
        }
    }
}

// Fused QKV GEMM. grid (18, 128): x -> (wsel, col tile) [wave-shared in L2],
// y -> 256-row tile. Writes bf16 hi/lo splits.
__global__ __launch_bounds__(512) void mma_gemm_qkv(
    const bf16* __restrict__ Xhi, const bf16* __restrict__ Xlo,
    const bf16* __restrict__ Whi, const bf16* __restrict__ Wlo,
    const float* __restrict__ bq, const float* __restrict__ bk,
    const float* __restrict__ bv,
    bf16* __restrict__ qhi, bf16* __restrict__ qlo,
    bf16* __restrict__ khi, bf16* __restrict__ klo,
    bf16* __restrict__ vhi, bf16* __restrict__ vlo)
{
    extern __shared__ char smem[];
    const uint32_t sbase = smem_u32(smem);

    const int wsel = blockIdx.x / 6;
    const int col0 = (blockIdx.x % 6) * 128;
    const int row0 = blockIdx.y * 256;
    const size_t WSZ = (size_t)EMBED * EMBED;

    const bf16* Bh = Whi + (size_t)wsel * WSZ;
    const bf16* Bl = Wlo + (size_t)wsel * WSZ;
    const float* bias = (wsel == 0) ? bq : (wsel == 1) ? bk : bv;
    bf16* Yhi = (wsel == 0) ? qhi : (wsel == 1) ? khi : vhi;
    bf16* Ylo = (wsel == 0) ? qlo : (wsel == 1) ? klo : vlo;
    const float scale = (wsel == 0) ? 0.125f : 1.f;

    float acc[4][4][4];
    #pragma unroll
    for (int mt = 0; mt < 4; mt++)
        #pragma unroll
        for (int nt = 0; nt < 4; nt++)
            #pragma unroll
            for (int u = 0; u < 4; u++) acc[mt][nt][u] = 0.f;

    gemm_mainloop(Xhi, Xlo, Bh, Bl, row0, col0, sbase, acc);

    const int lane = threadIdx.x & 31;
    const int wid  = threadIdx.x >> 5;
    const int wm   = wid >> 2;
    const int wn   = wid & 3;

    #pragma unroll
    for (int mt = 0; mt < 4; mt++) {
        int r0 = row0 + wm * 64 + mt * 16 + (lane >> 2);
        #pragma unroll
        for (int nt = 0; nt < 4; nt++) {
            int mcol = col0 + wn * 32 + nt * 8 + 2 * (lane & 3);
            float b0 = bias[mcol], b1 = bias[mcol + 1];
            float o0 = (acc[mt][nt][0] + b0) * scale;
            float o1 = (acc[mt][nt][1] + b1) * scale;
            float o2 = (acc[mt][nt][2] + b0) * scale;
            float o3 = (acc[mt][nt][3] + b1) * scale;
            bf16 h0 = __float2bfloat16(o0), h1 = __float2bfloat16(o1);
            bf16 h2 = __float2bfloat16(o2), h3 = __float2bfloat16(o3);
            *(bf162*)(Yhi + (size_t)r0 * EMBED + mcol) = bf162(h0, h1);
            *(bf162*)(Yhi + (size_t)(r0 + 8) * EMBED + mcol) = bf162(h2, h3);
            bf16 l0 = __float2bfloat16(o0 - __bfloat162float(h0));
            bf16 l1 = __float2bfloat16(o1 - __bfloat162float(h1));
            bf16 l2 = __float2bfloat16(o2 - __bfloat162float(h2));
            bf16 l3 = __float2bfloat16(o3 - __bfloat162float(h3));
            *(bf162*)(Ylo + (size_t)r0 * EMBED + mcol) = bf162(l0, l1);
            *(bf162*)(Ylo + (size_t)(r0 + 8) * EMBED + mcol) = bf162(l2, l3);
        }
    }
}

// Output-projection GEMM: grid (6, 128), f32 output.
__global__ __launch_bounds__(512) void mma_gemm_out(
    const bf16* __restrict__ Ahi, const bf16* __restrict__ Alo,
    const bf16* __restrict__ Bhi, const bf16* __restrict__ Blo,
    const float* __restrict__ bias, float* __restrict__ Yf)
{
    extern __shared__ char smem[];
    const uint32_t sbase = smem_u32(smem);
    const int col0 = blockIdx.x * 128;
    const int row0 = blockIdx.y * 256;

    float acc[4][4][4];
    #pragma unroll
    for (int mt = 0; mt < 4; mt++)
        #pragma unroll
        for (int nt = 0; nt < 4; nt++)
            #pragma unroll
            for (int u = 0; u < 4; u++) acc[mt][nt][u] = 0.f;

    gemm_mainloop(Ahi, Alo, Bhi, Blo, row0, col0, sbase, acc);

    const int lane = threadIdx.x & 31;
    const int wid  = threadIdx.x >> 5;
    const int wm   = wid >> 2;
    const int wn   = wid & 3;

    #pragma unroll
    for (int mt = 0; mt < 4; mt++) {
        int r0 = row0 + wm * 64 + mt * 16 + (lane >> 2);
        #pragma unroll
        for (int nt = 0; nt < 4; nt++) {
            int mcol = col0 + wn * 32 + nt * 8 + 2 * (lane & 3);
            float b0 = bias[mcol], b1 = bias[mcol + 1];
            *(float2*)(Yf + (size_t)r0 * EMBED + mcol) =
                make_float2(acc[mt][nt][0] + b0, acc[mt][nt][1] + b1);
            *(float2*)(Yf + (size_t)(r0 + 8) * EMBED + mcol) =
                make_float2(acc[mt][nt][2] + b0, acc[mt][nt][3] + b1);
        }
    }
}

// ---------------------------------------------------------------------------
// Attention via mma.sync (unchanged from R8): 96KB smem, 2 CTAs/SM,
// P tiles overlay dead Q/K tiles after QK^T.
// ---------------------------------------------------------------------------
#define AT_QHI 0
#define AT_QLO 16384
#define AT_KHI 32768
#define AT_KLO 49152
#define AT_VHI 65536
#define AT_VLO 81920
#define AT_PHI 0
#define AT_PLO 32768
#define AT_MKW 98304
#define AT_SMEM (98304 + 32)

__device__ __forceinline__ uint32_t qswz(int r, int c) {
    return (uint32_t)(r * 128 + ((c ^ (r & 7)) * 16));
}
__device__ __forceinline__ uint32_t pswz(int r, int c) {
    return (uint32_t)(r * 256 + (((c & 8) | ((c & 7) ^ (r & 7))) * 16));
}

__global__ __launch_bounds__(256) void attn_mma(
    const bf16* __restrict__ qhi, const bf16* __restrict__ qlo,
    const bf16* __restrict__ khi, const bf16* __restrict__ klo,
    const bf16* __restrict__ vhi, const bf16* __restrict__ vlo,
    const unsigned char* __restrict__ mask, float* __restrict__ probs,
    bf16* __restrict__ chi, bf16* __restrict__ clo, int write_probs)
{
    extern __shared__ char smc[];
    const uint32_t sb = smem_u32(smc);

    const int c = blockIdx.x;
    const int h = blockIdx.y;
    const int tid = threadIdx.x;
    const int wid = tid >> 5;
    const int lane = tid & 31;
    const size_t base = (size_t)c * EMBED + h * DKK;

    {
        const bf16* srcs[6] = { qhi, qlo, khi, klo, vhi, vlo };
        #pragma unroll
        for (int t = 0; t < 6; t++) {
            #pragma unroll
            for (int it = 0; it < 4; it++) {
                int e = tid + it * 256;
                int r = e >> 3;
                int ch = e & 7;
                CP_ASYNC16(sb + (uint32_t)(t * 16384) + qswz(r, ch),
                           srcs[t] + (size_t)r * (CDIM * EMBED) + base + ch * 8);
            }
        }
        CP_COMMIT();
    }
    if (tid < 4) {
        uint32_t w = 0;
        for (int b = 0; b < 32; b++)
            if (mask[(size_t)(tid * 32 + b) * CDIM + c]) w |= (1u << b);
        *(uint32_t*)(smc + AT_MKW + tid * 4) = w;
    }
    CP_WAIT0();
    __syncthreads();

    const int i0 = wid * 16;

    float acc[16][4];
    #pragma unroll
    for (int nt = 0; nt < 16; nt++)
        #pragma unroll
        for (int u = 0; u < 4; u++) acc[nt][u] = 0.f;

    #pragma unroll
    for (int ks = 0; ks < 4; ks++) {
        uint32_t ah[4], al[4];
        {
            int rr = i0 + (lane & 15);
            int cc = 2 * ks + (lane >> 4);
            uint32_t ad = sb + AT_QHI + qswz(rr, cc);
            ldsm4(ah, ad);
            ldsm4(al, ad + 16384);
        }
        #pragma unroll
        for (int jg = 0; jg < 8; jg++) {
            int jr = jg * 16 + ((lane & 16) >> 1) + (lane & 7);
            int cc = 2 * ks + ((lane >> 3) & 1);
            uint32_t bd = sb + AT_KHI + qswz(jr, cc);
            uint32_t bh[4], bl[4];
            ldsm4(bh, bd);
            ldsm4(bl, bd + 16384);
            mma16816(acc[2 * jg], ah, bh[0], bh[1]);
            mma16816(acc[2 * jg], ah, bl[0], bl[1]);
            mma16816(acc[2 * jg], al, bh[0], bh[1]);
            mma16816(acc[2 * jg + 1], ah, bh[2], bh[3]);
            mma16816(acc[2 * jg + 1], ah, bl[2], bl[3]);
            mma16816(acc[2 * jg + 1], al, bh[2], bh[3]);
        }
    }

    // All warps must finish reading Q/K before P overlays them.
    __syncthreads();

    {
        uint32_t mw[4];
        #pragma unroll
        for (int u = 0; u < 4; u++) mw[u] = *(const uint32_t*)(smc + AT_MKW + u * 4);
        const int jb = (lane & 3) * 2;

        float mxl = -1e30f, mxh = -1e30f;
        #pragma unroll
        for (int nt = 0; nt < 16; nt++) {
            int j0 = nt * 8 + jb;
            bool m0 = (mw[j0 >> 5] >> (j0 & 31)) & 1;
            bool m1 = (mw[j0 >> 5] >> ((j0 + 1) & 31)) & 1;
            if (m0) { acc[nt][0] = -10000.f; acc[nt][2] = -10000.f; }
            if (m1) { acc[nt][1] = -10000.f; acc[nt][3] = -10000.f; }
            mxl = fmaxf(mxl, fmaxf(acc[nt][0], acc[nt][1]));
            mxh = fmaxf(mxh, fmaxf(acc[nt][2], acc[nt][3]));
        }
        #pragma unroll
        for (int o = 1; o <= 2; o <<= 1) {
            mxl = fmaxf(mxl, __shfl_xor_sync(0xffffffffu, mxl, o));
            mxh = fmaxf(mxh, __shfl_xor_sync(0xffffffffu, mxh, o));
        }
        float sl = 0.f, sh = 0.f;
        #pragma unroll
        for (int nt = 0; nt < 16; nt++) {
            acc[nt][0] = __expf(acc[nt][0] - mxl);
            acc[nt][1] = __expf(acc[nt][1] - mxl);
            acc[nt][2] = __expf(acc[nt][2] - mxh);
            acc[nt][3] = __expf(acc[nt][3] - mxh);
            sl += acc[nt][0] + acc[nt][1];
            sh += acc[nt][2] + acc[nt][3];
        }
        #pragma unroll
        for (int o = 1; o <= 2; o <<= 1) {
            sl += __shfl_xor_sync(0xffffffffu, sl, o);
            sh += __shfl_xor_sync(0xffffffffu, sh, o);
        }
        float il = 1.f / sl, ih = 1.f / sh;

        const int rl = i0 + (lane >> 2);
        #pragma unroll
        for (int nt = 0; nt < 16; nt++) {
            float p0 = acc[nt][0] * il;
            float p1 = acc[nt][1] * il;
            float p2 = acc[nt][2] * ih;
            float p3 = acc[nt][3] * ih;
            bf16 h0 = __float2bfloat16(p0), h1 = __float2bfloat16(p1);
            bf16 h2 = __float2bfloat16(p2), h3 = __float2bfloat16(p3);
            uint32_t a0 = pswz(rl, nt) + (uint32_t)(jb * 2);
            uint32_t a1 = pswz(rl + 8, nt) + (uint32_t)(jb * 2);
            *(bf162*)(smc + AT_PHI + a0) = bf162(h0, h1);
            *(bf162*)(smc + AT_PHI + a1) = bf162(h2, h3);
            bf16 l0 = __float2bfloat16(p0 - __bfloat162float(h0));
            bf16 l1 = __float2bfloat16(p1 - __bfloat162float(h1));
            bf16 l2 = __float2bfloat16(p2 - __bfloat162float(h2));
            bf16 l3 = __float2bfloat16(p3 - __bfloat162float(h3));
            *(bf162*)(smc + AT_PLO + a0) = bf162(l0, l1);
            *(bf162*)(smc + AT_PLO + a1) = bf162(l2, l3);
        }
    }
    __syncthreads();

    if (write_probs) {
        const size_t pb = ((size_t)(h * CDIM + c) * RDIM) * RDIM;
        #pragma unroll
        for (int it = 0; it < 16; it++) {
            int e = tid + it * 256;
            int r = e >> 5;
            int s2 = e & 31;
            uint32_t pa = pswz(r, s2 >> 1) + (uint32_t)((s2 & 1) * 8);
            uint2 uh = *(const uint2*)(smc + AT_PHI + pa);
            uint2 ul = *(const uint2*)(smc + AT_PLO + pa);
            bf162 h0 = *(bf162*)&uh.x, h1 = *(bf162*)&uh.y;
            bf162 l0 = *(bf162*)&ul.x, l1 = *(bf162*)&ul.y;
            float4 o;
            o.x = __bfloat162float(h0.x) + __bfloat162float(l0.x);
            o.y = __bfloat162float(h0.y) + __bfloat162float(l0.y);
            o.z = __bfloat162float(h1.x) + __bfloat162float(l1.x);
            o.w = __bfloat162float(h1.y) + __bfloat162float(l1.y);
            *(float4*)(probs + pb + (size_t)r * RDIM + s2 * 4) = o;
        }
    }

    float acc2[8][4];
    #pragma unroll
    for (int nt = 0; nt < 8; nt++)
        #pragma unroll
        for (int u = 0; u < 4; u++) acc2[nt][u] = 0.f;

    #pragma unroll
    for (int j16 = 0; j16 < 8; j16++) {
        uint32_t ph4[4], pl4[4];
        {
            int rr = i0 + (lane & 15);
            int cc = 2 * j16 + (lane >> 4);
            uint32_t ad = sb + AT_PHI + pswz(rr, cc);
            ldsm4(ph4, ad);
            ldsm4(pl4, ad + 32768);
        }
        #pragma unroll
        for (int dg = 0; dg < 4; dg++) {
            int jr = j16 * 16 + (lane & 7) + ((lane >> 3) & 1) * 8;
            int cc = 2 * dg + (lane >> 4);
            uint32_t vd = sb + AT_VHI + qswz(jr, cc);
            uint32_t vh4[4], vl4[4];
            ldsm4t(vh4, vd);
            ldsm4t(vl4, vd + 16384);
            mma16816(acc2[2 * dg], ph4, vh4[0], vh4[1]);
            mma16816(acc2[2 * dg], ph4, vl4[0], vl4[1]);
            mma16816(acc2[2 * dg], pl4, vh4[0], vh4[1]);
            mma16816(acc2[2 * dg + 1], ph4, vh4[2], vh4[3]);
            mma16816(acc2[2 * dg + 1], ph4, vl4[2], vl4[3]);
            mma16816(acc2[2 * dg + 1], pl4, vh4[2], vh4[3]);
        }
    }

    {
        const int r0 = i0 + (lane >> 2);
        #pragma unroll
        for (int nt = 0; nt < 8; nt++) {
            int d0 = nt * 8 + (lane & 3) * 2;
            float o0 = acc2[nt][0], o1 = acc2[nt][1];
            float o2 = acc2[nt][2], o3 = acc2[nt][3];
            bf16 h0 = __float2bfloat16(o0), h1 = __float2bfloat16(o1);
            bf16 h2 = __float2bfloat16(o2), h3 = __float2bfloat16(o3);
            size_t g0 = (size_t)r0 * (CDIM * EMBED) + base + d0;
            size_t g1 = (size_t)(r0 + 8) * (CDIM * EMBED) + base + d0;
            *(bf162*)(chi + g0) = bf162(h0, h1);
            *(bf162*)(chi + g1) = bf162(h2, h3);
            bf16 l0 = __float2bfloat16(o0 - __bfloat162float(h0));
            bf16 l1 = __float2bfloat16(o1 - __bfloat162float(h1));
            bf16 l2 = __float2bfloat16(o2 - __bfloat162float(h2));
            bf16 l3 = __float2bfloat16(o3 - __bfloat162float(h3));
            *(bf162*)(clo + g0) = bf162(l0, l1);
            *(bf162*)(clo + g1) = bf162(l2, l3);
        }
    }
}

// ---------------------------------------------------------------------------
extern "C" void kernel_launch(void* const* d_in, const int* in_sizes, int n_in,
                              void* d_out, int out_size)
{
    const float* x  = (const float*)d_in[0];
    const unsigned char* mask = (const unsigned char*)d_in[1];
    const float* Wq = (const float*)d_in[2];
    const float* bq = (const float*)d_in[3];
    const float* Wk = (const float*)d_in[4];
    const float* bk = (const float*)d_in[5];
    const float* Wv = (const float*)d_in[6];
    const float* bv = (const float*)d_in[7];
    const float* Wo = (const float*)d_in[8];
    const float* bo = (const float*)d_in[9];
    float* out = (float*)d_out;

    bf16 *xhi, *xlo, *qhi, *qlo, *khi, *klo, *vhi, *vlo, *whi, *wlo;
    cudaGetSymbolAddress((void**)&xhi, g_xhi);
    cudaGetSymbolAddress((void**)&xlo, g_xlo);
    cudaGetSymbolAddress((void**)&qhi, g_qhi);
    cudaGetSymbolAddress((void**)&qlo, g_qlo);
    cudaGetSymbolAddress((void**)&khi, g_khi);
    cudaGetSymbolAddress((void**)&klo, g_klo);
    cudaGetSymbolAddress((void**)&vhi, g_vhi);
    cudaGetSymbolAddress((void**)&vlo, g_vlo);
    cudaGetSymbolAddress((void**)&whi, g_whi);
    cudaGetSymbolAddress((void**)&wlo, g_wlo);

    const long long out_elems = (long long)NTOK * EMBED;
    const long long probs_elems = (long long)HEADS * CDIM * RDIM * RDIM;
    int write_probs = ((long long)out_size >= out_elems + probs_elems) ? 1 : 0;
    float* probs = write_probs ? (out + out_elems) : nullptr;

    cudaFuncSetAttribute(mma_gemm_qkv, cudaFuncAttributeMaxDynamicSharedMemorySize, GSMEM);
    cudaFuncSetAttribute(mma_gemm_out, cudaFuncAttributeMaxDynamicSharedMemorySize, GSMEM);
    cudaFuncSetAttribute(attn_mma, cudaFuncAttributeMaxDynamicSharedMemorySize, AT_SMEM);

    const size_t WSZ = (size_t)EMBED * EMBED;
    const int xn4 = (int)(((size_t)NTOK * EMBED) / 4);
    const int wn4 = (int)(WSZ / 4);

    split_kernel<<<(xn4 + 255) / 256, 256>>>((const float4*)x, xhi, xlo, xn4);
    {
        dim3 wgrid((wn4 + 255) / 256, 4);
        split_w_kernel<<<wgrid, 256>>>((const float4*)Wq, (const float4*)Wk,
                                       (const float4*)Wv, (const float4*)Wo,
                                       whi, wlo, wn4);
    }

    dim3 qkvgrid(18, NTOK / 256);          // (18, 128)
    mma_gemm_qkv<<<qkvgrid, 512, GSMEM>>>(xhi, xlo, whi, wlo,
                                          bq, bk, bv,
                                          qhi, qlo, khi, klo, vhi, vlo);

    dim3 agrid(CDIM, HEADS);
    attn_mma<<<agrid, 256, AT_SMEM>>>(qhi, qlo, khi, klo, vhi, vlo,
                                      mask, probs, xhi, xlo, write_probs);

    dim3 ogrid(EMBED / 128, NTOK / 256);   // (6, 128)
    mma_gemm_out<<<ogrid, 512, GSMEM>>>(xhi, xlo, whi + 3 * WSZ, wlo + 3 * WSZ,
                                        bo, out);
}

// round 11
// speedup vs baseline: 1.0750x; 1.0750x over previous
#include <cuda_runtime.h>
#include <cuda_bf16.h>
#include <cstdint>

#define EMBED 768
#define HEADS 12
#define DKK   64
#define RDIM  128
#define CDIM  256
#define NTOK  (RDIM * CDIM)   // 32768

typedef __nv_bfloat16 bf16;
typedef __nv_bfloat162 bf162;

__device__ bf16 g_xhi[(size_t)NTOK * EMBED];
__device__ bf16 g_xlo[(size_t)NTOK * EMBED];
__device__ bf16 g_qhi[(size_t)NTOK * EMBED];
__device__ bf16 g_qlo[(size_t)NTOK * EMBED];
__device__ bf16 g_khi[(size_t)NTOK * EMBED];
__device__ bf16 g_klo[(size_t)NTOK * EMBED];
__device__ bf16 g_vhi[(size_t)NTOK * EMBED];
__device__ bf16 g_vlo[(size_t)NTOK * EMBED];
__device__ bf16 g_whi[4 * (size_t)EMBED * EMBED];
__device__ bf16 g_wlo[4 * (size_t)EMBED * EMBED];

__device__ __forceinline__ uint32_t smem_u32(const void* p) {
    uint32_t a;
    asm("{ .reg .u64 t; cvta.to.shared.u64 t, %1; cvt.u32.u64 %0, t; }"
        : "=r"(a) : "l"(p));
    return a;
}

__device__ __forceinline__ void ldsm4(uint32_t (&r)[4], uint32_t addr) {
    asm volatile("ldmatrix.sync.aligned.m8n8.x4.shared.b16 {%0,%1,%2,%3}, [%4];"
                 : "=r"(r[0]), "=r"(r[1]), "=r"(r[2]), "=r"(r[3]) : "r"(addr));
}

__device__ __forceinline__ void ldsm4t(uint32_t (&r)[4], uint32_t addr) {
    asm volatile("ldmatrix.sync.aligned.m8n8.x4.trans.shared.b16 {%0,%1,%2,%3}, [%4];"
                 : "=r"(r[0]), "=r"(r[1]), "=r"(r[2]), "=r"(r[3]) : "r"(addr));
}

__device__ __forceinline__ void mma16816(float (&c)[4], const uint32_t (&a)[4],
                                         uint32_t b0, uint32_t b1) {
    asm volatile(
        "mma.sync.aligned.m16n8k16.row.col.f32.bf16.bf16.f32 "
        "{%0,%1,%2,%3}, {%4,%5,%6,%7}, {%8,%9}, {%0,%1,%2,%3};"
        : "+f"(c[0]), "+f"(c[1]), "+f"(c[2]), "+f"(c[3])
        : "r"(a[0]), "r"(a[1]), "r"(a[2]), "r"(a[3]), "r"(b0), "r"(b1));
}

#define CP_ASYNC16(dst, src) \
    asm volatile("cp.async.cg.shared.global [%0], [%1], 16;" \
                 :: "r"(dst), "l"(src))
#define CP_COMMIT() asm volatile("cp.async.commit_group;" ::: "memory")
#define CP_WAIT0()  asm volatile("cp.async.wait_group 0;" ::: "memory")

// ---------------------------------------------------------------------------
__device__ __forceinline__ void split4(const float4 v, bf162* hp, bf162* lp) {
    bf16 h0 = __float2bfloat16(v.x);
    bf16 h1 = __float2bfloat16(v.y);
    bf16 h2 = __float2bfloat16(v.z);
    bf16 h3 = __float2bfloat16(v.w);
    bf16 l0 = __float2bfloat16(v.x - __bfloat162float(h0));
    bf16 l1 = __float2bfloat16(v.y - __bfloat162float(h1));
    bf16 l2 = __float2bfloat16(v.z - __bfloat162float(h2));
    bf16 l3 = __float2bfloat16(v.w - __bfloat162float(h3));
    hp[0] = bf162(h0, h1);
    hp[1] = bf162(h2, h3);
    lp[0] = bf162(l0, l1);
    lp[1] = bf162(l2, l3);
}

__global__ __launch_bounds__(256) void split_kernel(
    const float4* __restrict__ src, bf16* __restrict__ hi,
    bf16* __restrict__ lo, int n4)
{
    int i = blockIdx.x * blockDim.x + threadIdx.x;
    if (i >= n4) return;
    split4(src[i], (bf162*)(hi + (size_t)i * 4), (bf162*)(lo + (size_t)i * 4));
}

__global__ __launch_bounds__(256) void split_w_kernel(
    const float4* __restrict__ w0, const float4* __restrict__ w1,
    const float4* __restrict__ w2, const float4* __restrict__ w3,
    bf16* __restrict__ hi, bf16* __restrict__ lo, int n4)
{
    int i = blockIdx.x * blockDim.x + threadIdx.x;
    if (i >= n4) return;
    const float4* src = (blockIdx.y == 0) ? w0 : (blockIdx.y == 1) ? w1 :
                        (blockIdx.y == 2) ? w2 : w3;
    size_t o = (size_t)blockIdx.y * n4 * 4 + (size_t)i * 4;
    split4(src[i], (bf162*)(hi + o), (bf162*)(lo + o));
}

// ---------------------------------------------------------------------------
// mma.sync split-bf16 GEMM mainloop (R8 config: CTA 128x128, 8 warps,
// warp tile 64x32, K-chunk 32, cp.async double-buffered smem, 2 CTAs/SM).
// ---------------------------------------------------------------------------
#define KC      32
#define NCH     (EMBED / KC)          // 24
#define ROWB    80
#define TILEB   (128 * ROWB)          // 10240 B
#define STAGEB  (4 * TILEB)           // 40960
#define GSMEM   (2 * STAGEB)          // 81920

__device__ __forceinline__ void gemm_mainloop(
    const bf16* __restrict__ Ahi, const bf16* __restrict__ Alo,
    const bf16* __restrict__ Bhi, const bf16* __restrict__ Blo,
    int row0, int col0, uint32_t sbase, float (&acc)[4][4][4])
{
    const int tid  = threadIdx.x;
    const int wid  = tid >> 5;
    const int lane = tid & 31;
    const int wm   = wid >> 2;
    const int wn   = wid & 3;

    const uint32_t a_off = (uint32_t)((lane & 15) * ROWB + (lane >> 4) * 16);
    const uint32_t b_off = (uint32_t)((((lane & 16) >> 1) + (lane & 7)) * ROWB +
                                      (((lane >> 3) & 1) * 16));

    auto load_stage = [&](int s, int c) {
        uint32_t stage = sbase + s * STAGEB;
        #pragma unroll
        for (int it = 0; it < 8; it++) {
            int u = tid + it * 256;
            int t = u >> 9;
            int rem = u & 511;
            int r = rem >> 2;
            int g = rem & 3;
            const bf16* src;
            int grow;
            if (t == 0)      { src = Ahi; grow = row0 + r; }
            else if (t == 1) { src = Alo; grow = row0 + r; }
            else if (t == 2) { src = Bhi; grow = col0 + r; }
            else             { src = Blo; grow = col0 + r; }
            CP_ASYNC16(stage + (uint32_t)(t * TILEB + r * ROWB + g * 16),
                       src + (size_t)grow * EMBED + c * KC + g * 8);
        }
    };

    load_stage(0, 0);
    CP_COMMIT();

    for (int c = 0; c < NCH; c++) {
        const int s = c & 1;
        CP_WAIT0();
        __syncthreads();
        if (c + 1 < NCH) { load_stage(s ^ 1, c + 1); CP_COMMIT(); }

        const uint32_t st = sbase + s * STAGEB;
        #pragma unroll
        for (int ks = 0; ks < 2; ks++) {
            const uint32_t kb = (uint32_t)(ks * 32);
            uint32_t ah[4][4], al[4][4];
            uint32_t bh[4][2], bl[4][2];
            #pragma unroll
            for (int mt = 0; mt < 4; mt++) {
                uint32_t ra = st + (uint32_t)((wm * 64 + mt * 16) * ROWB) + kb + a_off;
                ldsm4(ah[mt], ra);
                ldsm4(al[mt], ra + TILEB);
            }
            #pragma unroll
            for (int np = 0; np < 2; np++) {
                uint32_t rb = st + 2 * TILEB +
                              (uint32_t)((wn * 32 + np * 16) * ROWB) + kb + b_off;
                uint32_t rh[4], rl[4];
                ldsm4(rh, rb);
                ldsm4(rl, rb + TILEB);
                bh[2 * np][0] = rh[0]; bh[2 * np][1] = rh[1];
                bh[2 * np + 1][0] = rh[2]; bh[2 * np + 1][1] = rh[3];
                bl[2 * np][0] = rl[0]; bl[2 * np][1] = rl[1];
                bl[2 * np + 1][0] = rl[2]; bl[2 * np + 1][1] = rl[3];
            }
            #pragma unroll
            for (int mt = 0; mt < 4; mt++)
                #pragma unroll
                for (int nt = 0; nt < 4; nt++) {
                    mma16816(acc[mt][nt], ah[mt], bh[nt][0], bh[nt][1]);
                    mma16816(acc[mt][nt], ah[mt], bl[nt][0], bl[nt][1]);
                    mma16816(acc[mt][nt], al[mt], bh[nt][0], bh[nt][1]);
                }
        }
    }
}

// Fused QKV GEMM. grid (18, 256): x -> (wsel, col tile) [wave-shared in L2],
// y -> 128-row tile. Writes bf16 hi/lo splits.
__global__ __launch_bounds__(256) void mma_gemm_qkv(
    const bf16* __restrict__ Xhi, const bf16* __restrict__ Xlo,
    const bf16* __restrict__ Whi, const bf16* __restrict__ Wlo,
    const float* __restrict__ bq, const float* __restrict__ bk,
    const float* __restrict__ bv,
    bf16* __restrict__ qhi, bf16* __restrict__ qlo,
    bf16* __restrict__ khi, bf16* __restrict__ klo,
    bf16* __restrict__ vhi, bf16* __restrict__ vlo)
{
    extern __shared__ char smem[];
    const uint32_t sbase = smem_u32(smem);

    const int wsel = blockIdx.x / 6;
    const int col0 = (blockIdx.x % 6) * 128;
    const int row0 = blockIdx.y * 128;
    const size_t WSZ = (size_t)EMBED * EMBED;

    const bf16* Bh = Whi + (size_t)wsel * WSZ;
    const bf16* Bl = Wlo + (size_t)wsel * WSZ;
    const float* bias = (wsel == 0) ? bq : (wsel == 1) ? bk : bv;
    bf16* Yhi = (wsel == 0) ? qhi : (wsel == 1) ? khi : vhi;
    bf16* Ylo = (wsel == 0) ? qlo : (wsel == 1) ? klo : vlo;
    const float scale = (wsel == 0) ? 0.125f : 1.f;

    float acc[4][4][4];
    #pragma unroll
    for (int mt = 0; mt < 4; mt++)
        #pragma unroll
        for (int nt = 0; nt < 4; nt++)
            #pragma unroll
            for (int u = 0; u < 4; u++) acc[mt][nt][u] = 0.f;

    gemm_mainloop(Xhi, Xlo, Bh, Bl, row0, col0, sbase, acc);

    const int lane = threadIdx.x & 31;
    const int wid  = threadIdx.x >> 5;
    const int wm   = wid >> 2;
    const int wn   = wid & 3;

    #pragma unroll
    for (int mt = 0; mt < 4; mt++) {
        int r0 = row0 + wm * 64 + mt * 16 + (lane >> 2);
        #pragma unroll
        for (int nt = 0; nt < 4; nt++) {
            int mcol = col0 + wn * 32 + nt * 8 + 2 * (lane & 3);
            float b0 = bias[mcol], b1 = bias[mcol + 1];
            float o0 = (acc[mt][nt][0] + b0) * scale;
            float o1 = (acc[mt][nt][1] + b1) * scale;
            float o2 = (acc[mt][nt][2] + b0) * scale;
            float o3 = (acc[mt][nt][3] + b1) * scale;
            bf16 h0 = __float2bfloat16(o0), h1 = __float2bfloat16(o1);
            bf16 h2 = __float2bfloat16(o2), h3 = __float2bfloat16(o3);
            *(bf162*)(Yhi + (size_t)r0 * EMBED + mcol) = bf162(h0, h1);
            *(bf162*)(Yhi + (size_t)(r0 + 8) * EMBED + mcol) = bf162(h2, h3);
            bf16 l0 = __float2bfloat16(o0 - __bfloat162float(h0));
            bf16 l1 = __float2bfloat16(o1 - __bfloat162float(h1));
            bf16 l2 = __float2bfloat16(o2 - __bfloat162float(h2));
            bf16 l3 = __float2bfloat16(o3 - __bfloat162float(h3));
            *(bf162*)(Ylo + (size_t)r0 * EMBED + mcol) = bf162(l0, l1);
            *(bf162*)(Ylo + (size_t)(r0 + 8) * EMBED + mcol) = bf162(l2, l3);
        }
    }
}

// Output-projection GEMM: grid (6, 256), f32 output.
__global__ __launch_bounds__(256) void mma_gemm_out(
    const bf16* __restrict__ Ahi, const bf16* __restrict__ Alo,
    const bf16* __restrict__ Bhi, const bf16* __restrict__ Blo,
    const float* __restrict__ bias, float* __restrict__ Yf)
{
    extern __shared__ char smem[];
    const uint32_t sbase = smem_u32(smem);
    const int col0 = blockIdx.x * 128;
    const int row0 = blockIdx.y * 128;

    float acc[4][4][4];
    #pragma unroll
    for (int mt = 0; mt < 4; mt++)
        #pragma unroll
        for (int nt = 0; nt < 4; nt++)
            #pragma unroll
            for (int u = 0; u < 4; u++) acc[mt][nt][u] = 0.f;

    gemm_mainloop(Ahi, Alo, Bhi, Blo, row0, col0, sbase, acc);

    const int lane = threadIdx.x & 31;
    const int wid  = threadIdx.x >> 5;
    const int wm   = wid >> 2;
    const int wn   = wid & 3;

    #pragma unroll
    for (int mt = 0; mt < 4; mt++) {
        int r0 = row0 + wm * 64 + mt * 16 + (lane >> 2);
        #pragma unroll
        for (int nt = 0; nt < 4; nt++) {
            int mcol = col0 + wn * 32 + nt * 8 + 2 * (lane & 3);
            float b0 = bias[mcol], b1 = bias[mcol + 1];
            *(float2*)(Yf + (size_t)r0 * EMBED + mcol) =
                make_float2(acc[mt][nt][0] + b0, acc[mt][nt][1] + b1);
            *(float2*)(Yf + (size_t)(r0 + 8) * EMBED + mcol) =
                make_float2(acc[mt][nt][2] + b0, acc[mt][nt][3] + b1);
        }
    }
}

// ---------------------------------------------------------------------------
// Attention via mma.sync (R8 config): 96KB smem, 2 CTAs/SM,
// P tiles overlay dead Q/K tiles after QK^T.
// ---------------------------------------------------------------------------
#define AT_QHI 0
#define AT_QLO 16384
#define AT_KHI 32768
#define AT_KLO 49152
#define AT_VHI 65536
#define AT_VLO 81920
#define AT_PHI 0
#define AT_PLO 32768
#define AT_MKW 98304
#define AT_SMEM (98304 + 32)

__device__ __forceinline__ uint32_t qswz(int r, int c) {
    return (uint32_t)(r * 128 + ((c ^ (r & 7)) * 16));
}
__device__ __forceinline__ uint32_t pswz(int r, int c) {
    return (uint32_t)(r * 256 + (((c & 8) | ((c & 7) ^ (r & 7))) * 16));
}

__global__ __launch_bounds__(256) void attn_mma(
    const bf16* __restrict__ qhi, const bf16* __restrict__ qlo,
    const bf16* __restrict__ khi, const bf16* __restrict__ klo,
    const bf16* __restrict__ vhi, const bf16* __restrict__ vlo,
    const unsigned char* __restrict__ mask, float* __restrict__ probs,
    bf16* __restrict__ chi, bf16* __restrict__ clo, int write_probs)
{
    extern __shared__ char smc[];
    const uint32_t sb = smem_u32(smc);

    const int c = blockIdx.x;
    const int h = blockIdx.y;
    const int tid = threadIdx.x;
    const int wid = tid >> 5;
    const int lane = tid & 31;
    const size_t base = (size_t)c * EMBED + h * DKK;

    {
        const bf16* srcs[6] = { qhi, qlo, khi, klo, vhi, vlo };
        #pragma unroll
        for (int t = 0; t < 6; t++) {
            #pragma unroll
            for (int it = 0; it < 4; it++) {
                int e = tid + it * 256;
                int r = e >> 3;
                int ch = e & 7;
                CP_ASYNC16(sb + (uint32_t)(t * 16384) + qswz(r, ch),
                           srcs[t] + (size_t)r * (CDIM * EMBED) + base + ch * 8);
            }
        }
        CP_COMMIT();
    }
    if (tid < 4) {
        uint32_t w = 0;
        for (int b = 0; b < 32; b++)
            if (mask[(size_t)(tid * 32 + b) * CDIM + c]) w |= (1u << b);
        *(uint32_t*)(smc + AT_MKW + tid * 4) = w;
    }
    CP_WAIT0();
    __syncthreads();

    const int i0 = wid * 16;

    float acc[16][4];
    #pragma unroll
    for (int nt = 0; nt < 16; nt++)
        #pragma unroll
        for (int u = 0; u < 4; u++) acc[nt][u] = 0.f;

    #pragma unroll
    for (int ks = 0; ks < 4; ks++) {
        uint32_t ah[4], al[4];
        {
            int rr = i0 + (lane & 15);
            int cc = 2 * ks + (lane >> 4);
            uint32_t ad = sb + AT_QHI + qswz(rr, cc);
            ldsm4(ah, ad);
            ldsm4(al, ad + 16384);
        }
        #pragma unroll
        for (int jg = 0; jg < 8; jg++) {
            int jr = jg * 16 + ((lane & 16) >> 1) + (lane & 7);
            int cc = 2 * ks + ((lane >> 3) & 1);
            uint32_t bd = sb + AT_KHI + qswz(jr, cc);
            uint32_t bh[4], bl[4];
            ldsm4(bh, bd);
            ldsm4(bl, bd + 16384);
            mma16816(acc[2 * jg], ah, bh[0], bh[1]);
            mma16816(acc[2 * jg], ah, bl[0], bl[1]);
            mma16816(acc[2 * jg], al, bh[0], bh[1]);
            mma16816(acc[2 * jg + 1], ah, bh[2], bh[3]);
            mma16816(acc[2 * jg + 1], ah, bl[2], bl[3]);
            mma16816(acc[2 * jg + 1], al, bh[2], bh[3]);
        }
    }

    // All warps must finish reading Q/K before P overlays them.
    __syncthreads();

    {
        uint32_t mw[4];
        #pragma unroll
        for (int u = 0; u < 4; u++) mw[u] = *(const uint32_t*)(smc + AT_MKW + u * 4);
        const int jb = (lane & 3) * 2;

        float mxl = -1e30f, mxh = -1e30f;
        #pragma unroll
        for (int nt = 0; nt < 16; nt++) {
            int j0 = nt * 8 + jb;
            bool m0 = (mw[j0 >> 5] >> (j0 & 31)) & 1;
            bool m1 = (mw[j0 >> 5] >> ((j0 + 1) & 31)) & 1;
            if (m0) { acc[nt][0] = -10000.f; acc[nt][2] = -10000.f; }
            if (m1) { acc[nt][1] = -10000.f; acc[nt][3] = -10000.f; }
            mxl = fmaxf(mxl, fmaxf(acc[nt][0], acc[nt][1]));
            mxh = fmaxf(mxh, fmaxf(acc[nt][2], acc[nt][3]));
        }
        #pragma unroll
        for (int o = 1; o <= 2; o <<= 1) {
            mxl = fmaxf(mxl, __shfl_xor_sync(0xffffffffu, mxl, o));
            mxh = fmaxf(mxh, __shfl_xor_sync(0xffffffffu, mxh, o));
        }
        float sl = 0.f, sh = 0.f;
        #pragma unroll
        for (int nt = 0; nt < 16; nt++) {
            acc[nt][0] = __expf(acc[nt][0] - mxl);
            acc[nt][1] = __expf(acc[nt][1] - mxl);
            acc[nt][2] = __expf(acc[nt][2] - mxh);
            acc[nt][3] = __expf(acc[nt][3] - mxh);
            sl += acc[nt][0] + acc[nt][1];
            sh += acc[nt][2] + acc[nt][3];
        }
        #pragma unroll
        for (int o = 1; o <= 2; o <<= 1) {
            sl += __shfl_xor_sync(0xffffffffu, sl, o);
            sh += __shfl_xor_sync(0xffffffffu, sh, o);
        }
        float il = 1.f / sl, ih = 1.f / sh;

        const int rl = i0 + (lane >> 2);
        #pragma unroll
        for (int nt = 0; nt < 16; nt++) {
            float p0 = acc[nt][0] * il;
            float p1 = acc[nt][1] * il;
            float p2 = acc[nt][2] * ih;
            float p3 = acc[nt][3] * ih;
            bf16 h0 = __float2bfloat16(p0), h1 = __float2bfloat16(p1);
            bf16 h2 = __float2bfloat16(p2), h3 = __float2bfloat16(p3);
            uint32_t a0 = pswz(rl, nt) + (uint32_t)(jb * 2);
            uint32_t a1 = pswz(rl + 8, nt) + (uint32_t)(jb * 2);
            *(bf162*)(smc + AT_PHI + a0) = bf162(h0, h1);
            *(bf162*)(smc + AT_PHI + a1) = bf162(h2, h3);
            bf16 l0 = __float2bfloat16(p0 - __bfloat162float(h0));
            bf16 l1 = __float2bfloat16(p1 - __bfloat162float(h1));
            bf16 l2 = __float2bfloat16(p2 - __bfloat162float(h2));
            bf16 l3 = __float2bfloat16(p3 - __bfloat162float(h3));
            *(bf162*)(smc + AT_PLO + a0) = bf162(l0, l1);
            *(bf162*)(smc + AT_PLO + a1) = bf162(l2, l3);
        }
    }
    __syncthreads();

    if (write_probs) {
        const size_t pb = ((size_t)(h * CDIM + c) * RDIM) * RDIM;
        #pragma unroll
        for (int it = 0; it < 16; it++) {
            int e = tid + it * 256;
            int r = e >> 5;
            int s2 = e & 31;
            uint32_t pa = pswz(r, s2 >> 1) + (uint32_t)((s2 & 1) * 8);
            uint2 uh = *(const uint2*)(smc + AT_PHI + pa);
            uint2 ul = *(const uint2*)(smc + AT_PLO + pa);
            bf162 h0 = *(bf162*)&uh.x, h1 = *(bf162*)&uh.y;
            bf162 l0 = *(bf162*)&ul.x, l1 = *(bf162*)&ul.y;
            float4 o;
            o.x = __bfloat162float(h0.x) + __bfloat162float(l0.x);
            o.y = __bfloat162float(h0.y) + __bfloat162float(l0.y);
            o.z = __bfloat162float(h1.x) + __bfloat162float(l1.x);
            o.w = __bfloat162float(h1.y) + __bfloat162float(l1.y);
            *(float4*)(probs + pb + (size_t)r * RDIM + s2 * 4) = o;
        }
    }

    float acc2[8][4];
    #pragma unroll
    for (int nt = 0; nt < 8; nt++)
        #pragma unroll
        for (int u = 0; u < 4; u++) acc2[nt][u] = 0.f;

    #pragma unroll
    for (int j16 = 0; j16 < 8; j16++) {
        uint32_t ph4[4], pl4[4];
        {
            int rr = i0 + (lane & 15);
            int cc = 2 * j16 + (lane >> 4);
            uint32_t ad = sb + AT_PHI + pswz(rr, cc);
            ldsm4(ph4, ad);
            ldsm4(pl4, ad + 32768);
        }
        #pragma unroll
        for (int dg = 0; dg < 4; dg++) {
            int jr = j16 * 16 + (lane & 7) + ((lane >> 3) & 1) * 8;
            int cc = 2 * dg + (lane >> 4);
            uint32_t vd = sb + AT_VHI + qswz(jr, cc);
            uint32_t vh4[4], vl4[4];
            ldsm4t(vh4, vd);
            ldsm4t(vl4, vd + 16384);
            mma16816(acc2[2 * dg], ph4, vh4[0], vh4[1]);
            mma16816(acc2[2 * dg], ph4, vl4[0], vl4[1]);
            mma16816(acc2[2 * dg], pl4, vh4[0], vh4[1]);
            mma16816(acc2[2 * dg + 1], ph4, vh4[2], vh4[3]);
            mma16816(acc2[2 * dg + 1], ph4, vl4[2], vl4[3]);
            mma16816(acc2[2 * dg + 1], pl4, vh4[2], vh4[3]);
        }
    }

    {
        const int r0 = i0 + (lane >> 2);
        #pragma unroll
        for (int nt = 0; nt < 8; nt++) {
            int d0 = nt * 8 + (lane & 3) * 2;
            float o0 = acc2[nt][0], o1 = acc2[nt][1];
            float o2 = acc2[nt][2], o3 = acc2[nt][3];
            bf16 h0 = __float2bfloat16(o0), h1 = __float2bfloat16(o1);
            bf16 h2 = __float2bfloat16(o2), h3 = __float2bfloat16(o3);
            size_t g0 = (size_t)r0 * (CDIM * EMBED) + base + d0;
            size_t g1 = (size_t)(r0 + 8) * (CDIM * EMBED) + base + d0;
            *(bf162*)(chi + g0) = bf162(h0, h1);
            *(bf162*)(chi + g1) = bf162(h2, h3);
            bf16 l0 = __float2bfloat16(o0 - __bfloat162float(h0));
            bf16 l1 = __float2bfloat16(o1 - __bfloat162float(h1));
            bf16 l2 = __float2bfloat16(o2 - __bfloat162float(h2));
            bf16 l3 = __float2bfloat16(o3 - __bfloat162float(h3));
            *(bf162*)(clo + g0) = bf162(l0, l1);
            *(bf162*)(clo + g1) = bf162(l2, l3);
        }
    }
}

// ---------------------------------------------------------------------------
extern "C" void kernel_launch(void* const* d_in, const int* in_sizes, int n_in,
                              void* d_out, int out_size)
{
    const float* x  = (const float*)d_in[0];
    const unsigned char* mask = (const unsigned char*)d_in[1];
    const float* Wq = (const float*)d_in[2];
    const float* bq = (const float*)d_in[3];
    const float* Wk = (const float*)d_in[4];
    const float* bk = (const float*)d_in[5];
    const float* Wv = (const float*)d_in[6];
    const float* bv = (const float*)d_in[7];
    const float* Wo = (const float*)d_in[8];
    const float* bo = (const float*)d_in[9];
    float* out = (float*)d_out;

    bf16 *xhi, *xlo, *qhi, *qlo, *khi, *klo, *vhi, *vlo, *whi, *wlo;
    cudaGetSymbolAddress((void**)&xhi, g_xhi);
    cudaGetSymbolAddress((void**)&xlo, g_xlo);
    cudaGetSymbolAddress((void**)&qhi, g_qhi);
    cudaGetSymbolAddress((void**)&qlo, g_qlo);
    cudaGetSymbolAddress((void**)&khi, g_khi);
    cudaGetSymbolAddress((void**)&klo, g_klo);
    cudaGetSymbolAddress((void**)&vhi, g_vhi);
    cudaGetSymbolAddress((void**)&vlo, g_vlo);
    cudaGetSymbolAddress((void**)&whi, g_whi);
    cudaGetSymbolAddress((void**)&wlo, g_wlo);

    const long long out_elems = (long long)NTOK * EMBED;
    const long long probs_elems = (long long)HEADS * CDIM * RDIM * RDIM;
    int write_probs = ((long long)out_size >= out_elems + probs_elems) ? 1 : 0;
    float* probs = write_probs ? (out + out_elems) : nullptr;

    cudaFuncSetAttribute(mma_gemm_qkv, cudaFuncAttributeMaxDynamicSharedMemorySize, GSMEM);
    cudaFuncSetAttribute(mma_gemm_out, cudaFuncAttributeMaxDynamicSharedMemorySize, GSMEM);
    cudaFuncSetAttribute(attn_mma, cudaFuncAttributeMaxDynamicSharedMemorySize, AT_SMEM);

    const size_t WSZ = (size_t)EMBED * EMBED;
    const int xn4 = (int)(((size_t)NTOK * EMBED) / 4);
    const int wn4 = (int)(WSZ / 4);

    split_kernel<<<(xn4 + 255) / 256, 256>>>((const float4*)x, xhi, xlo, xn4);
    {
        dim3 wgrid((wn4 + 255) / 256, 4);
        split_w_kernel<<<wgrid, 256>>>((const float4*)Wq, (const float4*)Wk,
                                       (const float4*)Wv, (const float4*)Wo,
                                       whi, wlo, wn4);
    }

    dim3 qkvgrid(18, NTOK / 128);          // (18, 256): col/wsel fastest
    mma_gemm_qkv<<<qkvgrid, 256, GSMEM>>>(xhi, xlo, whi, wlo,
                                          bq, bk, bv,
                                          qhi, qlo, khi, klo, vhi, vlo);

    dim3 agrid(CDIM, HEADS);
    attn_mma<<<agrid, 256, AT_SMEM>>>(qhi, qlo, khi, klo, vhi, vlo,
                                      mask, probs, xhi, xlo, write_probs);

    dim3 ogrid(EMBED / 128, NTOK / 128);   // (6, 256)
    mma_gemm_out<<<ogrid, 256, GSMEM>>>(xhi, xlo, whi + 3 * WSZ, wlo + 3 * WSZ,
                                        bo, out);
}

// round 14
// speedup vs baseline: 1.1813x; 1.0988x over previous
#include <cuda_runtime.h>
#include <cuda_bf16.h>
#include <cstdint>

#define EMBED 768
#define HEADS 12
#define DKK   64
#define RDIM  128
#define CDIM  256
#define NTOK  (RDIM * CDIM)   // 32768

typedef __nv_bfloat16 bf16;
typedef __nv_bfloat162 bf162;

__device__ bf16 g_xhi[(size_t)NTOK * EMBED];
__device__ bf16 g_xlo[(size_t)NTOK * EMBED];
__device__ bf16 g_qhi[(size_t)NTOK * EMBED];
__device__ bf16 g_qlo[(size_t)NTOK * EMBED];
__device__ bf16 g_khi[(size_t)NTOK * EMBED];
__device__ bf16 g_klo[(size_t)NTOK * EMBED];
__device__ bf16 g_vhi[(size_t)NTOK * EMBED];
__device__ bf16 g_vlo[(size_t)NTOK * EMBED];
__device__ bf16 g_whi[4 * (size_t)EMBED * EMBED];
__device__ bf16 g_wlo[4 * (size_t)EMBED * EMBED];

__device__ __forceinline__ uint32_t smem_u32(const void* p) {
    uint32_t a;
    asm("{ .reg .u64 t; cvta.to.shared.u64 t, %1; cvt.u32.u64 %0, t; }"
        : "=r"(a) : "l"(p));
    return a;
}

__device__ __forceinline__ void ldsm4(uint32_t (&r)[4], uint32_t addr) {
    asm volatile("ldmatrix.sync.aligned.m8n8.x4.shared.b16 {%0,%1,%2,%3}, [%4];"
                 : "=r"(r[0]), "=r"(r[1]), "=r"(r[2]), "=r"(r[3]) : "r"(addr));
}

__device__ __forceinline__ void ldsm4t(uint32_t (&r)[4], uint32_t addr) {
    asm volatile("ldmatrix.sync.aligned.m8n8.x4.trans.shared.b16 {%0,%1,%2,%3}, [%4];"
                 : "=r"(r[0]), "=r"(r[1]), "=r"(r[2]), "=r"(r[3]) : "r"(addr));
}

__device__ __forceinline__ void mma16816(float (&c)[4], const uint32_t (&a)[4],
                                         uint32_t b0, uint32_t b1) {
    asm volatile(
        "mma.sync.aligned.m16n8k16.row.col.f32.bf16.bf16.f32 "
        "{%0,%1,%2,%3}, {%4,%5,%6,%7}, {%8,%9}, {%0,%1,%2,%3};"
        : "+f"(c[0]), "+f"(c[1]), "+f"(c[2]), "+f"(c[3])
        : "r"(a[0]), "r"(a[1]), "r"(a[2]), "r"(a[3]), "r"(b0), "r"(b1));
}

#define CP_ASYNC16(dst, src) \
    asm volatile("cp.async.cg.shared.global [%0], [%1], 16;" \
                 :: "r"(dst), "l"(src))
#define CP_COMMIT() asm volatile("cp.async.commit_group;" ::: "memory")
#define CP_WAIT0()  asm volatile("cp.async.wait_group 0;" ::: "memory")
#define CP_WAIT1()  asm volatile("cp.async.wait_group 1;" ::: "memory")

// ---------------------------------------------------------------------------
__device__ __forceinline__ void split4(const float4 v, bf162* hp, bf162* lp) {
    bf16 h0 = __float2bfloat16(v.x);
    bf16 h1 = __float2bfloat16(v.y);
    bf16 h2 = __float2bfloat16(v.z);
    bf16 h3 = __float2bfloat16(v.w);
    bf16 l0 = __float2bfloat16(v.x - __bfloat162float(h0));
    bf16 l1 = __float2bfloat16(v.y - __bfloat162float(h1));
    bf16 l2 = __float2bfloat16(v.z - __bfloat162float(h2));
    bf16 l3 = __float2bfloat16(v.w - __bfloat162float(h3));
    hp[0] = bf162(h0, h1);
    hp[1] = bf162(h2, h3);
    lp[0] = bf162(l0, l1);
    lp[1] = bf162(l2, l3);
}

__global__ __launch_bounds__(256) void split_kernel(
    const float4* __restrict__ src, bf16* __restrict__ hi,
    bf16* __restrict__ lo, int n4)
{
    int i = blockIdx.x * blockDim.x + threadIdx.x;
    if (i >= n4) return;
    split4(src[i], (bf162*)(hi + (size_t)i * 4), (bf162*)(lo + (size_t)i * 4));
}

__global__ __launch_bounds__(256) void split_w_kernel(
    const float4* __restrict__ w0, const float4* __restrict__ w1,
    const float4* __restrict__ w2, const float4* __restrict__ w3,
    bf16* __restrict__ hi, bf16* __restrict__ lo, int n4)
{
    int i = blockIdx.x * blockDim.x + threadIdx.x;
    if (i >= n4) return;
    const float4* src = (blockIdx.y == 0) ? w0 : (blockIdx.y == 1) ? w1 :
                        (blockIdx.y == 2) ? w2 : w3;
    size_t o = (size_t)blockIdx.y * n4 * 4 + (size_t)i * 4;
    split4(src[i], (bf162*)(hi + o), (bf162*)(lo + o));
}

// ---------------------------------------------------------------------------
// mma.sync split-bf16 GEMM. CTA 128x128, 8 warps (warp tile 64x32), K-chunk 32.
// Tiles: 128 rows x 64B (swizzled, no padding). Swizzle: chunk' = c ^ ((r>>1)&3)
// -> conflict-free ldmatrix for both A and B lane patterns.
// 3-stage cp.async pipeline, prefetch distance 2, 96KB smem -> 2 CTAs/SM.
// ---------------------------------------------------------------------------
#define KC      32
#define NCH     (EMBED / KC)          // 24
#define TILEB   (128 * 64)            // 8192 B
#define STAGEB  (4 * TILEB)           // 32768
#define GSMEM   (3 * STAGEB)          // 98304

__device__ __forceinline__ uint32_t gswz(int r, int c) {
    return (uint32_t)(r * 64 + ((c ^ ((r >> 1) & 3)) << 4));
}

__device__ __forceinline__ void gemm_mainloop(
    const bf16* __restrict__ Ahi, const bf16* __restrict__ Alo,
    const bf16* __restrict__ Bhi, const bf16* __restrict__ Blo,
    int row0, int col0, uint32_t sbase, float (&acc)[4][4][4])
{
    const int tid  = threadIdx.x;
    const int wid  = tid >> 5;
    const int lane = tid & 31;
    const int wm   = wid >> 2;
    const int wn   = wid & 3;

    const int arl = lane & 15;                               // A row within 16
    const int acl = lane >> 4;                               // A chunk bit
    const int brl = ((lane & 16) >> 1) + (lane & 7);         // B row within 16
    const int bcl = (lane >> 3) & 1;                         // B chunk bit

    auto load_stage = [&](int s, int c) {
        uint32_t stage = sbase + s * STAGEB;
        #pragma unroll
        for (int it = 0; it < 8; it++) {
            int u = tid + it * 256;          // 0..2047 (16B units)
            int t = u >> 9;
            int rem = u & 511;
            int r = rem >> 2;
            int g = rem & 3;
            const bf16* src;
            int grow;
            if (t == 0)      { src = Ahi; grow = row0 + r; }
            else if (t == 1) { src = Alo; grow = row0 + r; }
            else if (t == 2) { src = Bhi; grow = col0 + r; }
            else             { src = Blo; grow = col0 + r; }
            CP_ASYNC16(stage + (uint32_t)(t * TILEB) + gswz(r, g),
                       src + (size_t)grow * EMBED + c * KC + g * 8);
        }
    };

    load_stage(0, 0);
    CP_COMMIT();
    load_stage(1, 1);
    CP_COMMIT();

    int s = 0;
    for (int c = 0; c < NCH; c++) {
        if (c == NCH - 1) { CP_WAIT0(); } else { CP_WAIT1(); }
        __syncthreads();
        if (c + 2 < NCH) {
            int ns = s + 2;
            if (ns >= 3) ns -= 3;
            load_stage(ns, c + 2);
        }
        CP_COMMIT();   // empty commits near the end keep group accounting simple

        const uint32_t st = sbase + s * STAGEB;
        #pragma unroll
        for (int ks = 0; ks < 2; ks++) {
            uint32_t ah[4][4], al[4][4];
            uint32_t bh[4][2], bl[4][2];
            #pragma unroll
            for (int mt = 0; mt < 4; mt++) {
                uint32_t ra = st + gswz(wm * 64 + mt * 16 + arl, 2 * ks + acl);
                ldsm4(ah[mt], ra);
                ldsm4(al[mt], ra + TILEB);
            }
            #pragma unroll
            for (int np = 0; np < 2; np++) {
                uint32_t rb = st + 2 * TILEB +
                              gswz(wn * 32 + np * 16 + brl, 2 * ks + bcl);
                uint32_t rh[4], rl[4];
                ldsm4(rh, rb);
                ldsm4(rl, rb + TILEB);
                bh[2 * np][0] = rh[0]; bh[2 * np][1] = rh[1];
                bh[2 * np + 1][0] = rh[2]; bh[2 * np + 1][1] = rh[3];
                bl[2 * np][0] = rl[0]; bl[2 * np][1] = rl[1];
                bl[2 * np + 1][0] = rl[2]; bl[2 * np + 1][1] = rl[3];
            }
            #pragma unroll
            for (int mt = 0; mt < 4; mt++)
                #pragma unroll
                for (int nt = 0; nt < 4; nt++) {
                    mma16816(acc[mt][nt], ah[mt], bh[nt][0], bh[nt][1]);
                    mma16816(acc[mt][nt], ah[mt], bl[nt][0], bl[nt][1]);
                    mma16816(acc[mt][nt], al[mt], bh[nt][0], bh[nt][1]);
                }
        }
        s = (s == 2) ? 0 : s + 1;
    }
}

// Fused QKV GEMM. grid (18, 256): x -> (wsel, col tile), y -> 128-row tile.
__global__ __launch_bounds__(256) void mma_gemm_qkv(
    const bf16* __restrict__ Xhi, const bf16* __restrict__ Xlo,
    const bf16* __restrict__ Whi, const bf16* __restrict__ Wlo,
    const float* __restrict__ bq, const float* __restrict__ bk,
    const float* __restrict__ bv,
    bf16* __restrict__ qhi, bf16* __restrict__ qlo,
    bf16* __restrict__ khi, bf16* __restrict__ klo,
    bf16* __restrict__ vhi, bf16* __restrict__ vlo)
{
    extern __shared__ char smem[];
    const uint32_t sbase = smem_u32(smem);

    const int wsel = blockIdx.x / 6;
    const int col0 = (blockIdx.x % 6) * 128;
    const int row0 = blockIdx.y * 128;
    const size_t WSZ = (size_t)EMBED * EMBED;

    const bf16* Bh = Whi + (size_t)wsel * WSZ;
    const bf16* Bl = Wlo + (size_t)wsel * WSZ;
    const float* bias = (wsel == 0) ? bq : (wsel == 1) ? bk : bv;
    bf16* Yhi = (wsel == 0) ? qhi : (wsel == 1) ? khi : vhi;
    bf16* Ylo = (wsel == 0) ? qlo : (wsel == 1) ? klo : vlo;
    const float scale = (wsel == 0) ? 0.125f : 1.f;

    float acc[4][4][4];
    #pragma unroll
    for (int mt = 0; mt < 4; mt++)
        #pragma unroll
        for (int nt = 0; nt < 4; nt++)
            #pragma unroll
            for (int u = 0; u < 4; u++) acc[mt][nt][u] = 0.f;

    gemm_mainloop(Xhi, Xlo, Bh, Bl, row0, col0, sbase, acc);

    const int lane = threadIdx.x & 31;
    const int wid  = threadIdx.x >> 5;
    const int wm   = wid >> 2;
    const int wn   = wid & 3;

    #pragma unroll
    for (int mt = 0; mt < 4; mt++) {
        int r0 = row0 + wm * 64 + mt * 16 + (lane >> 2);
        #pragma unroll
        for (int nt = 0; nt < 4; nt++) {
            int mcol = col0 + wn * 32 + nt * 8 + 2 * (lane & 3);
            float b0 = bias[mcol], b1 = bias[mcol + 1];
            float o0 = (acc[mt][nt][0] + b0) * scale;
            float o1 = (acc[mt][nt][1] + b1) * scale;
            float o2 = (acc[mt][nt][2] + b0) * scale;
            float o3 = (acc[mt][nt][3] + b1) * scale;
            bf16 h0 = __float2bfloat16(o0), h1 = __float2bfloat16(o1);
            bf16 h2 = __float2bfloat16(o2), h3 = __float2bfloat16(o3);
            *(bf162*)(Yhi + (size_t)r0 * EMBED + mcol) = bf162(h0, h1);
            *(bf162*)(Yhi + (size_t)(r0 + 8) * EMBED + mcol) = bf162(h2, h3);
            bf16 l0 = __float2bfloat16(o0 - __bfloat162float(h0));
            bf16 l1 = __float2bfloat16(o1 - __bfloat162float(h1));
            bf16 l2 = __float2bfloat16(o2 - __bfloat162float(h2));
            bf16 l3 = __float2bfloat16(o3 - __bfloat162float(h3));
            *(bf162*)(Ylo + (size_t)r0 * EMBED + mcol) = bf162(l0, l1);
            *(bf162*)(Ylo + (size_t)(r0 + 8) * EMBED + mcol) = bf162(l2, l3);
        }
    }
}

// Output-projection GEMM: grid (6, 256), f32 output.
__global__ __launch_bounds__(256) void mma_gemm_out(
    const bf16* __restrict__ Ahi, const bf16* __restrict__ Alo,
    const bf16* __restrict__ Bhi, const bf16* __restrict__ Blo,
    const float* __restrict__ bias, float* __restrict__ Yf)
{
    extern __shared__ char smem[];
    const uint32_t sbase = smem_u32(smem);
    const int col0 = blockIdx.x * 128;
    const int row0 = blockIdx.y * 128;

    float acc[4][4][4];
    #pragma unroll
    for (int mt = 0; mt < 4; mt++)
        #pragma unroll
        for (int nt = 0; nt < 4; nt++)
            #pragma unroll
            for (int u = 0; u < 4; u++) acc[mt][nt][u] = 0.f;

    gemm_mainloop(Ahi, Alo, Bhi, Blo, row0, col0, sbase, acc);

    const int lane = threadIdx.x & 31;
    const int wid  = threadIdx.x >> 5;
    const int wm   = wid >> 2;
    const int wn   = wid & 3;

    #pragma unroll
    for (int mt = 0; mt < 4; mt++) {
        int r0 = row0 + wm * 64 + mt * 16 + (lane >> 2);
        #pragma unroll
        for (int nt = 0; nt < 4; nt++) {
            int mcol = col0 + wn * 32 + nt * 8 + 2 * (lane & 3);
            float b0 = bias[mcol], b1 = bias[mcol + 1];
            *(float2*)(Yf + (size_t)r0 * EMBED + mcol) =
                make_float2(acc[mt][nt][0] + b0, acc[mt][nt][1] + b1);
            *(float2*)(Yf + (size_t)(r0 + 8) * EMBED + mcol) =
                make_float2(acc[mt][nt][2] + b0, acc[mt][nt][3] + b1);
        }
    }
}

// ---------------------------------------------------------------------------
// Attention via mma.sync (unchanged, 96KB smem, 2 CTAs/SM).
// ---------------------------------------------------------------------------
#define AT_QHI 0
#define AT_QLO 16384
#define AT_KHI 32768
#define AT_KLO 49152
#define AT_VHI 65536
#define AT_VLO 81920
#define AT_PHI 0
#define AT_PLO 32768
#define AT_MKW 98304
#define AT_SMEM (98304 + 32)

__device__ __forceinline__ uint32_t qswz(int r, int c) {
    return (uint32_t)(r * 128 + ((c ^ (r & 7)) * 16));
}
__device__ __forceinline__ uint32_t pswz(int r, int c) {
    return (uint32_t)(r * 256 + (((c & 8) | ((c & 7) ^ (r & 7))) * 16));
}

__global__ __launch_bounds__(256) void attn_mma(
    const bf16* __restrict__ qhi, const bf16* __restrict__ qlo,
    const bf16* __restrict__ khi, const bf16* __restrict__ klo,
    const bf16* __restrict__ vhi, const bf16* __restrict__ vlo,
    const unsigned char* __restrict__ mask, float* __restrict__ probs,
    bf16* __restrict__ chi, bf16* __restrict__ clo, int write_probs)
{
    extern __shared__ char smc[];
    const uint32_t sb = smem_u32(smc);

    const int c = blockIdx.x;
    const int h = blockIdx.y;
    const int tid = threadIdx.x;
    const int wid = tid >> 5;
    const int lane = tid & 31;
    const size_t base = (size_t)c * EMBED + h * DKK;

    {
        const bf16* srcs[6] = { qhi, qlo, khi, klo, vhi, vlo };
        #pragma unroll
        for (int t = 0; t < 6; t++) {
            #pragma unroll
            for (int it = 0; it < 4; it++) {
                int e = tid + it * 256;
                int r = e >> 3;
                int ch = e & 7;
                CP_ASYNC16(sb + (uint32_t)(t * 16384) + qswz(r, ch),
                           srcs[t] + (size_t)r * (CDIM * EMBED) + base + ch * 8);
            }
        }
        CP_COMMIT();
    }
    if (tid < 4) {
        uint32_t w = 0;
        for (int b = 0; b < 32; b++)
            if (mask[(size_t)(tid * 32 + b) * CDIM + c]) w |= (1u << b);
        *(uint32_t*)(smc + AT_MKW + tid * 4) = w;
    }
    CP_WAIT0();
    __syncthreads();

    const int i0 = wid * 16;

    float acc[16][4];
    #pragma unroll
    for (int nt = 0; nt < 16; nt++)
        #pragma unroll
        for (int u = 0; u < 4; u++) acc[nt][u] = 0.f;

    #pragma unroll
    for (int ks = 0; ks < 4; ks++) {
        uint32_t ah[4], al[4];
        {
            int rr = i0 + (lane & 15);
            int cc = 2 * ks + (lane >> 4);
            uint32_t ad = sb + AT_QHI + qswz(rr, cc);
            ldsm4(ah, ad);
            ldsm4(al, ad + 16384);
        }
        #pragma unroll
        for (int jg = 0; jg < 8; jg++) {
            int jr = jg * 16 + ((lane & 16) >> 1) + (lane & 7);
            int cc = 2 * ks + ((lane >> 3) & 1);
            uint32_t bd = sb + AT_KHI + qswz(jr, cc);
            uint32_t bh[4], bl[4];
            ldsm4(bh, bd);
            ldsm4(bl, bd + 16384);
            mma16816(acc[2 * jg], ah, bh[0], bh[1]);
            mma16816(acc[2 * jg], ah, bl[0], bl[1]);
            mma16816(acc[2 * jg], al, bh[0], bh[1]);
            mma16816(acc[2 * jg + 1], ah, bh[2], bh[3]);
            mma16816(acc[2 * jg + 1], ah, bl[2], bl[3]);
            mma16816(acc[2 * jg + 1], al, bh[2], bh[3]);
        }
    }

    __syncthreads();

    {
        uint32_t mw[4];
        #pragma unroll
        for (int u = 0; u < 4; u++) mw[u] = *(const uint32_t*)(smc + AT_MKW + u * 4);
        const int jb = (lane & 3) * 2;

        float mxl = -1e30f, mxh = -1e30f;
        #pragma unroll
        for (int nt = 0; nt < 16; nt++) {
            int j0 = nt * 8 + jb;
            bool m0 = (mw[j0 >> 5] >> (j0 & 31)) & 1;
            bool m1 = (mw[j0 >> 5] >> ((j0 + 1) & 31)) & 1;
            if (m0) { acc[nt][0] = -10000.f; acc[nt][2] = -10000.f; }
            if (m1) { acc[nt][1] = -10000.f; acc[nt][3] = -10000.f; }
            mxl = fmaxf(mxl, fmaxf(acc[nt][0], acc[nt][1]));
            mxh = fmaxf(mxh, fmaxf(acc[nt][2], acc[nt][3]));
        }
        #pragma unroll
        for (int o = 1; o <= 2; o <<= 1) {
            mxl = fmaxf(mxl, __shfl_xor_sync(0xffffffffu, mxl, o));
            mxh = fmaxf(mxh, __shfl_xor_sync(0xffffffffu, mxh, o));
        }
        float sl = 0.f, sh = 0.f;
        #pragma unroll
        for (int nt = 0; nt < 16; nt++) {
            acc[nt][0] = __expf(acc[nt][0] - mxl);
            acc[nt][1] = __expf(acc[nt][1] - mxl);
            acc[nt][2] = __expf(acc[nt][2] - mxh);
            acc[nt][3] = __expf(acc[nt][3] - mxh);
            sl += acc[nt][0] + acc[nt][1];
            sh += acc[nt][2] + acc[nt][3];
        }
        #pragma unroll
        for (int o = 1; o <= 2; o <<= 1) {
            sl += __shfl_xor_sync(0xffffffffu, sl, o);
            sh += __shfl_xor_sync(0xffffffffu, sh, o);
        }
        float il = 1.f / sl, ih = 1.f / sh;

        const int rl = i0 + (lane >> 2);
        #pragma unroll
        for (int nt = 0; nt < 16; nt++) {
            float p0 = acc[nt][0] * il;
            float p1 = acc[nt][1] * il;
            float p2 = acc[nt][2] * ih;
            float p3 = acc[nt][3] * ih;
            bf16 h0 = __float2bfloat16(p0), h1 = __float2bfloat16(p1);
            bf16 h2 = __float2bfloat16(p2), h3 = __float2bfloat16(p3);
            uint32_t a0 = pswz(rl, nt) + (uint32_t)(jb * 2);
            uint32_t a1 = pswz(rl + 8, nt) + (uint32_t)(jb * 2);
            *(bf162*)(smc + AT_PHI + a0) = bf162(h0, h1);
            *(bf162*)(smc + AT_PHI + a1) = bf162(h2, h3);
            bf16 l0 = __float2bfloat16(p0 - __bfloat162float(h0));
            bf16 l1 = __float2bfloat16(p1 - __bfloat162float(h1));
            bf16 l2 = __float2bfloat16(p2 - __bfloat162float(h2));
            bf16 l3 = __float2bfloat16(p3 - __bfloat162float(h3));
            *(bf162*)(smc + AT_PLO + a0) = bf162(l0, l1);
            *(bf162*)(smc + AT_PLO + a1) = bf162(l2, l3);
        }
    }
    __syncthreads();

    if (write_probs) {
        const size_t pb = ((size_t)(h * CDIM + c) * RDIM) * RDIM;
        #pragma unroll
        for (int it = 0; it < 16; it++) {
            int e = tid + it * 256;
            int r = e >> 5;
            int s2 = e & 31;
            uint32_t pa = pswz(r, s2 >> 1) + (uint32_t)((s2 & 1) * 8);
            uint2 uh = *(const uint2*)(smc + AT_PHI + pa);
            uint2 ul = *(const uint2*)(smc + AT_PLO + pa);
            bf162 h0 = *(bf162*)&uh.x, h1 = *(bf162*)&uh.y;
            bf162 l0 = *(bf162*)&ul.x, l1 = *(bf162*)&ul.y;
            float4 o;
            o.x = __bfloat162float(h0.x) + __bfloat162float(l0.x);
            o.y = __bfloat162float(h0.y) + __bfloat162float(l0.y);
            o.z = __bfloat162float(h1.x) + __bfloat162float(l1.x);
            o.w = __bfloat162float(h1.y) + __bfloat162float(l1.y);
            *(float4*)(probs + pb + (size_t)r * RDIM + s2 * 4) = o;
        }
    }

    float acc2[8][4];
    #pragma unroll
    for (int nt = 0; nt < 8; nt++)
        #pragma unroll
        for (int u = 0; u < 4; u++) acc2[nt][u] = 0.f;

    #pragma unroll
    for (int j16 = 0; j16 < 8; j16++) {
        uint32_t ph4[4], pl4[4];
        {
            int rr = i0 + (lane & 15);
            int cc = 2 * j16 + (lane >> 4);
            uint32_t ad = sb + AT_PHI + pswz(rr, cc);
            ldsm4(ph4, ad);
            ldsm4(pl4, ad + 32768);
        }
        #pragma unroll
        for (int dg = 0; dg < 4; dg++) {
            int jr = j16 * 16 + (lane & 7) + ((lane >> 3) & 1) * 8;
            int cc = 2 * dg + (lane >> 4);
            uint32_t vd = sb + AT_VHI + qswz(jr, cc);
            uint32_t vh4[4], vl4[4];
            ldsm4t(vh4, vd);
            ldsm4t(vl4, vd + 16384);
            mma16816(acc2[2 * dg], ph4, vh4[0], vh4[1]);
            mma16816(acc2[2 * dg], ph4, vl4[0], vl4[1]);
            mma16816(acc2[2 * dg], pl4, vh4[0], vh4[1]);
            mma16816(acc2[2 * dg + 1], ph4, vh4[2], vh4[3]);
            mma16816(acc2[2 * dg + 1], ph4, vl4[2], vl4[3]);
            mma16816(acc2[2 * dg + 1], pl4, vh4[2], vh4[3]);
        }
    }

    {
        const int r0 = i0 + (lane >> 2);
        #pragma unroll
        for (int nt = 0; nt < 8; nt++) {
            int d0 = nt * 8 + (lane & 3) * 2;
            float o0 = acc2[nt][0], o1 = acc2[nt][1];
            float o2 = acc2[nt][2], o3 = acc2[nt][3];
            bf16 h0 = __float2bfloat16(o0), h1 = __float2bfloat16(o1);
            bf16 h2 = __float2bfloat16(o2), h3 = __float2bfloat16(o3);
            size_t g0 = (size_t)r0 * (CDIM * EMBED) + base + d0;
            size_t g1 = (size_t)(r0 + 8) * (CDIM * EMBED) + base + d0;
            *(bf162*)(chi + g0) = bf162(h0, h1);
            *(bf162*)(chi + g1) = bf162(h2, h3);
            bf16 l0 = __float2bfloat16(o0 - __bfloat162float(h0));
            bf16 l1 = __float2bfloat16(o1 - __bfloat162float(h1));
            bf16 l2 = __float2bfloat16(o2 - __bfloat162float(h2));
            bf16 l3 = __float2bfloat16(o3 - __bfloat162float(h3));
            *(bf162*)(clo + g0) = bf162(l0, l1);
            *(bf162*)(clo + g1) = bf162(l2, l3);
        }
    }
}

// ---------------------------------------------------------------------------
extern "C" void kernel_launch(void* const* d_in, const int* in_sizes, int n_in,
                              void* d_out, int out_size)
{
    const float* x  = (const float*)d_in[0];
    const unsigned char* mask = (const unsigned char*)d_in[1];
    const float* Wq = (const float*)d_in[2];
    const float* bq = (const float*)d_in[3];
    const float* Wk = (const float*)d_in[4];
    const float* bk = (const float*)d_in[5];
    const float* Wv = (const float*)d_in[6];
    const float* bv = (const float*)d_in[7];
    const float* Wo = (const float*)d_in[8];
    const float* bo = (const float*)d_in[9];
    float* out = (float*)d_out;

    bf16 *xhi, *xlo, *qhi, *qlo, *khi, *klo, *vhi, *vlo, *whi, *wlo;
    cudaGetSymbolAddress((void**)&xhi, g_xhi);
    cudaGetSymbolAddress((void**)&xlo, g_xlo);
    cudaGetSymbolAddress((void**)&qhi, g_qhi);
    cudaGetSymbolAddress((void**)&qlo, g_qlo);
    cudaGetSymbolAddress((void**)&khi, g_khi);
    cudaGetSymbolAddress((void**)&klo, g_klo);
    cudaGetSymbolAddress((void**)&vhi, g_vhi);
    cudaGetSymbolAddress((void**)&vlo, g_vlo);
    cudaGetSymbolAddress((void**)&whi, g_whi);
    cudaGetSymbolAddress((void**)&wlo, g_wlo);

    const long long out_elems = (long long)NTOK * EMBED;
    const long long probs_elems = (long long)HEADS * CDIM * RDIM * RDIM;
    int write_probs = ((long long)out_size >= out_elems + probs_elems) ? 1 : 0;
    float* probs = write_probs ? (out + out_elems) : nullptr;

    cudaFuncSetAttribute(mma_gemm_qkv, cudaFuncAttributeMaxDynamicSharedMemorySize, GSMEM);
    cudaFuncSetAttribute(mma_gemm_out, cudaFuncAttributeMaxDynamicSharedMemorySize, GSMEM);
    cudaFuncSetAttribute(attn_mma, cudaFuncAttributeMaxDynamicSharedMemorySize, AT_SMEM);

    const size_t WSZ = (size_t)EMBED * EMBED;
    const int xn4 = (int)(((size_t)NTOK * EMBED) / 4);
    const int wn4 = (int)(WSZ / 4);

    split_kernel<<<(xn4 + 255) / 256, 256>>>((const float4*)x, xhi, xlo, xn4);
    {
        dim3 wgrid((wn4 + 255) / 256, 4);
        split_w_kernel<<<wgrid, 256>>>((const float4*)Wq, (const float4*)Wk,
                                       (const float4*)Wv, (const float4*)Wo,
                                       whi, wlo, wn4);
    }

    dim3 qkvgrid(18, NTOK / 128);          // (18, 256)
    mma_gemm_qkv<<<qkvgrid, 256, GSMEM>>>(xhi, xlo, whi, wlo,
                                          bq, bk, bv,
                                          qhi, qlo, khi, klo, vhi, vlo);

    dim3 agrid(CDIM, HEADS);
    attn_mma<<<agrid, 256, AT_SMEM>>>(qhi, qlo, khi, klo, vhi, vlo,
                                      mask, probs, xhi, xlo, write_probs);

    dim3 ogrid(EMBED / 128, NTOK / 128);   // (6, 256)
    mma_gemm_out<<<ogrid, 256, GSMEM>>>(xhi, xlo, whi + 3 * WSZ, wlo + 3 * WSZ,
                                        bo, out);
}

// round 15
// speedup vs baseline: 1.2893x; 1.0914x over previous
#include <cuda_runtime.h>
#include <cuda_bf16.h>
#include <cstdint>

#define EMBED 768
#define HEADS 12
#define DKK   64
#define RDIM  128
#define CDIM  256
#define NTOK  (RDIM * CDIM)   // 32768

typedef __nv_bfloat16 bf16;
typedef __nv_bfloat162 bf162;

__device__ bf16 g_xhi[(size_t)NTOK * EMBED];
__device__ bf16 g_xlo[(size_t)NTOK * EMBED];
__device__ bf16 g_qhi[(size_t)NTOK * EMBED];
__device__ bf16 g_qlo[(size_t)NTOK * EMBED];
__device__ bf16 g_khi[(size_t)NTOK * EMBED];
__device__ bf16 g_klo[(size_t)NTOK * EMBED];
__device__ bf16 g_vhi[(size_t)NTOK * EMBED];
__device__ bf16 g_vlo[(size_t)NTOK * EMBED];
__device__ bf16 g_whi[4 * (size_t)EMBED * EMBED];
__device__ bf16 g_wlo[4 * (size_t)EMBED * EMBED];
__device__ float g_ctx[(size_t)NTOK * EMBED];   // fp32 attention context

__device__ __forceinline__ uint32_t smem_u32(const void* p) {
    uint32_t a;
    asm("{ .reg .u64 t; cvta.to.shared.u64 t, %1; cvt.u32.u64 %0, t; }"
        : "=r"(a) : "l"(p));
    return a;
}

__device__ __forceinline__ void ldsm4(uint32_t (&r)[4], uint32_t addr) {
    asm volatile("ldmatrix.sync.aligned.m8n8.x4.shared.b16 {%0,%1,%2,%3}, [%4];"
                 : "=r"(r[0]), "=r"(r[1]), "=r"(r[2]), "=r"(r[3]) : "r"(addr));
}

__device__ __forceinline__ void ldsm4t(uint32_t (&r)[4], uint32_t addr) {
    asm volatile("ldmatrix.sync.aligned.m8n8.x4.trans.shared.b16 {%0,%1,%2,%3}, [%4];"
                 : "=r"(r[0]), "=r"(r[1]), "=r"(r[2]), "=r"(r[3]) : "r"(addr));
}

__device__ __forceinline__ void mma16816(float (&c)[4], const uint32_t (&a)[4],
                                         uint32_t b0, uint32_t b1) {
    asm volatile(
        "mma.sync.aligned.m16n8k16.row.col.f32.bf16.bf16.f32 "
        "{%0,%1,%2,%3}, {%4,%5,%6,%7}, {%8,%9}, {%0,%1,%2,%3};"
        : "+f"(c[0]), "+f"(c[1]), "+f"(c[2]), "+f"(c[3])
        : "r"(a[0]), "r"(a[1]), "r"(a[2]), "r"(a[3]), "r"(b0), "r"(b1));
}

__device__ __forceinline__ void mma_tf32(float (&c)[4], const uint32_t (&a)[4],
                                         uint32_t b0, uint32_t b1) {
    asm volatile(
        "mma.sync.aligned.m16n8k8.row.col.f32.tf32.tf32.f32 "
        "{%0,%1,%2,%3}, {%4,%5,%6,%7}, {%8,%9}, {%0,%1,%2,%3};"
        : "+f"(c[0]), "+f"(c[1]), "+f"(c[2]), "+f"(c[3])
        : "r"(a[0]), "r"(a[1]), "r"(a[2]), "r"(a[3]), "r"(b0), "r"(b1));
}

#define CP_ASYNC16(dst, src) \
    asm volatile("cp.async.cg.shared.global [%0], [%1], 16;" \
                 :: "r"(dst), "l"(src))
#define CP_COMMIT() asm volatile("cp.async.commit_group;" ::: "memory")
#define CP_WAIT0()  asm volatile("cp.async.wait_group 0;" ::: "memory")
#define CP_WAIT1()  asm volatile("cp.async.wait_group 1;" ::: "memory")

// ---------------------------------------------------------------------------
__device__ __forceinline__ void split4(const float4 v, bf162* hp, bf162* lp) {
    bf16 h0 = __float2bfloat16(v.x);
    bf16 h1 = __float2bfloat16(v.y);
    bf16 h2 = __float2bfloat16(v.z);
    bf16 h3 = __float2bfloat16(v.w);
    bf16 l0 = __float2bfloat16(v.x - __bfloat162float(h0));
    bf16 l1 = __float2bfloat16(v.y - __bfloat162float(h1));
    bf16 l2 = __float2bfloat16(v.z - __bfloat162float(h2));
    bf16 l3 = __float2bfloat16(v.w - __bfloat162float(h3));
    hp[0] = bf162(h0, h1);
    hp[1] = bf162(h2, h3);
    lp[0] = bf162(l0, l1);
    lp[1] = bf162(l2, l3);
}

__global__ __launch_bounds__(256) void split_kernel(
    const float4* __restrict__ src, bf16* __restrict__ hi,
    bf16* __restrict__ lo, int n4)
{
    int i = blockIdx.x * blockDim.x + threadIdx.x;
    if (i >= n4) return;
    split4(src[i], (bf162*)(hi + (size_t)i * 4), (bf162*)(lo + (size_t)i * 4));
}

__global__ __launch_bounds__(256) void split_w_kernel(
    const float4* __restrict__ w0, const float4* __restrict__ w1,
    const float4* __restrict__ w2,
    bf16* __restrict__ hi, bf16* __restrict__ lo, int n4)
{
    int i = blockIdx.x * blockDim.x + threadIdx.x;
    if (i >= n4) return;
    const float4* src = (blockIdx.y == 0) ? w0 : (blockIdx.y == 1) ? w1 : w2;
    size_t o = (size_t)blockIdx.y * n4 * 4 + (size_t)i * 4;
    split4(src[i], (bf162*)(hi + o), (bf162*)(lo + o));
}

// ---------------------------------------------------------------------------
// bf16 split GEMM (QKV). CTA 128x128, 8 warps, K-chunk 32, 64B swizzled rows,
// 3-stage cp.async pipeline (prefetch distance 2), 96KB smem, 2 CTAs/SM.
// ---------------------------------------------------------------------------
#define KC      32
#define NCH     (EMBED / KC)          // 24
#define TILEB   (128 * 64)            // 8192 B
#define STAGEB  (4 * TILEB)           // 32768
#define GSMEM   (3 * STAGEB)          // 98304

__device__ __forceinline__ uint32_t gswz(int r, int c) {
    return (uint32_t)(r * 64 + ((c ^ ((r >> 1) & 3)) << 4));
}
// 128B-row swizzle (8 chunks/row) for the tf32 path
__device__ __forceinline__ uint32_t cswz(int r, int c) {
    return (uint32_t)(r * 128 + ((c ^ (r & 7)) << 4));
}

__device__ __forceinline__ void gemm_mainloop(
    const bf16* __restrict__ Ahi, const bf16* __restrict__ Alo,
    const bf16* __restrict__ Bhi, const bf16* __restrict__ Blo,
    int row0, int col0, uint32_t sbase, float (&acc)[4][4][4])
{
    const int tid  = threadIdx.x;
    const int wid  = tid >> 5;
    const int lane = tid & 31;
    const int wm   = wid >> 2;
    const int wn   = wid & 3;

    const int arl = lane & 15;
    const int acl = lane >> 4;
    const int brl = ((lane & 16) >> 1) + (lane & 7);
    const int bcl = (lane >> 3) & 1;

    auto load_stage = [&](int s, int c) {
        uint32_t stage = sbase + s * STAGEB;
        #pragma unroll
        for (int it = 0; it < 8; it++) {
            int u = tid + it * 256;
            int t = u >> 9;
            int rem = u & 511;
            int r = rem >> 2;
            int g = rem & 3;
            const bf16* src;
            int grow;
            if (t == 0)      { src = Ahi; grow = row0 + r; }
            else if (t == 1) { src = Alo; grow = row0 + r; }
            else if (t == 2) { src = Bhi; grow = col0 + r; }
            else             { src = Blo; grow = col0 + r; }
            CP_ASYNC16(stage + (uint32_t)(t * TILEB) + gswz(r, g),
                       src + (size_t)grow * EMBED + c * KC + g * 8);
        }
    };

    load_stage(0, 0);
    CP_COMMIT();
    load_stage(1, 1);
    CP_COMMIT();

    int s = 0;
    for (int c = 0; c < NCH; c++) {
        if (c == NCH - 1) { CP_WAIT0(); } else { CP_WAIT1(); }
        __syncthreads();
        if (c + 2 < NCH) {
            int ns = s + 2;
            if (ns >= 3) ns -= 3;
            load_stage(ns, c + 2);
        }
        CP_COMMIT();

        const uint32_t st = sbase + s * STAGEB;
        #pragma unroll
        for (int ks = 0; ks < 2; ks++) {
            uint32_t ah[4][4], al[4][4];
            uint32_t bh[4][2], bl[4][2];
            #pragma unroll
            for (int mt = 0; mt < 4; mt++) {
                uint32_t ra = st + gswz(wm * 64 + mt * 16 + arl, 2 * ks + acl);
                ldsm4(ah[mt], ra);
                ldsm4(al[mt], ra + TILEB);
            }
            #pragma unroll
            for (int np = 0; np < 2; np++) {
                uint32_t rb = st + 2 * TILEB +
                              gswz(wn * 32 + np * 16 + brl, 2 * ks + bcl);
                uint32_t rh[4], rl[4];
                ldsm4(rh, rb);
                ldsm4(rl, rb + TILEB);
                bh[2 * np][0] = rh[0]; bh[2 * np][1] = rh[1];
                bh[2 * np + 1][0] = rh[2]; bh[2 * np + 1][1] = rh[3];
                bl[2 * np][0] = rl[0]; bl[2 * np][1] = rl[1];
                bl[2 * np + 1][0] = rl[2]; bl[2 * np + 1][1] = rl[3];
            }
            #pragma unroll
            for (int mt = 0; mt < 4; mt++)
                #pragma unroll
                for (int nt = 0; nt < 4; nt++) {
                    mma16816(acc[mt][nt], ah[mt], bh[nt][0], bh[nt][1]);
                    mma16816(acc[mt][nt], ah[mt], bl[nt][0], bl[nt][1]);
                    mma16816(acc[mt][nt], al[mt], bh[nt][0], bh[nt][1]);
                }
        }
        s = (s == 2) ? 0 : s + 1;
    }
}

// Fused QKV GEMM. grid (18, 256). Writes bf16 hi/lo splits.
__global__ __launch_bounds__(256) void mma_gemm_qkv(
    const bf16* __restrict__ Xhi, const bf16* __restrict__ Xlo,
    const bf16* __restrict__ Whi, const bf16* __restrict__ Wlo,
    const float* __restrict__ bq, const float* __restrict__ bk,
    const float* __restrict__ bv,
    bf16* __restrict__ qhi, bf16* __restrict__ qlo,
    bf16* __restrict__ khi, bf16* __restrict__ klo,
    bf16* __restrict__ vhi, bf16* __restrict__ vlo)
{
    extern __shared__ char smem[];
    const uint32_t sbase = smem_u32(smem);

    const int wsel = blockIdx.x / 6;
    const int col0 = (blockIdx.x % 6) * 128;
    const int row0 = blockIdx.y * 128;
    const size_t WSZ = (size_t)EMBED * EMBED;

    const bf16* Bh = Whi + (size_t)wsel * WSZ;
    const bf16* Bl = Wlo + (size_t)wsel * WSZ;
    const float* bias = (wsel == 0) ? bq : (wsel == 1) ? bk : bv;
    bf16* Yhi = (wsel == 0) ? qhi : (wsel == 1) ? khi : vhi;
    bf16* Ylo = (wsel == 0) ? qlo : (wsel == 1) ? klo : vlo;
    const float scale = (wsel == 0) ? 0.125f : 1.f;

    float acc[4][4][4];
    #pragma unroll
    for (int mt = 0; mt < 4; mt++)
        #pragma unroll
        for (int nt = 0; nt < 4; nt++)
            #pragma unroll
            for (int u = 0; u < 4; u++) acc[mt][nt][u] = 0.f;

    gemm_mainloop(Xhi, Xlo, Bh, Bl, row0, col0, sbase, acc);

    const int lane = threadIdx.x & 31;
    const int wid  = threadIdx.x >> 5;
    const int wm   = wid >> 2;
    const int wn   = wid & 3;

    #pragma unroll
    for (int mt = 0; mt < 4; mt++) {
        int r0 = row0 + wm * 64 + mt * 16 + (lane >> 2);
        #pragma unroll
        for (int nt = 0; nt < 4; nt++) {
            int mcol = col0 + wn * 32 + nt * 8 + 2 * (lane & 3);
            float b0 = bias[mcol], b1 = bias[mcol + 1];
            float o0 = (acc[mt][nt][0] + b0) * scale;
            float o1 = (acc[mt][nt][1] + b1) * scale;
            float o2 = (acc[mt][nt][2] + b0) * scale;
            float o3 = (acc[mt][nt][3] + b1) * scale;
            bf16 h0 = __float2bfloat16(o0), h1 = __float2bfloat16(o1);
            bf16 h2 = __float2bfloat16(o2), h3 = __float2bfloat16(o3);
            *(bf162*)(Yhi + (size_t)r0 * EMBED + mcol) = bf162(h0, h1);
            *(bf162*)(Yhi + (size_t)(r0 + 8) * EMBED + mcol) = bf162(h2, h3);
            bf16 l0 = __float2bfloat16(o0 - __bfloat162float(h0));
            bf16 l1 = __float2bfloat16(o1 - __bfloat162float(h1));
            bf16 l2 = __float2bfloat16(o2 - __bfloat162float(h2));
            bf16 l3 = __float2bfloat16(o3 - __bfloat162float(h3));
            *(bf162*)(Ylo + (size_t)r0 * EMBED + mcol) = bf162(l0, l1);
            *(bf162*)(Ylo + (size_t)(r0 + 8) * EMBED + mcol) = bf162(l2, l3);
        }
    }
}

// ---------------------------------------------------------------------------
// Output-projection GEMM in single-pass TF32. A = fp32 context, B = raw fp32
// Wo (hardware truncates fp32 -> tf32 operands). K-chunk 32 fp32 = 4 k8 MMA
// steps; 64 MMAs/chunk/warp vs 96 for the bf16 3-pass path. Same 3-stage
// pipeline, stage = A(16KB) + B(16KB) = 32KB, 128B swizzled rows.
// ---------------------------------------------------------------------------
#define TILE32  16384
#define STAGE32 32768

__global__ __launch_bounds__(256) void mma_gemm_out(
    const float* __restrict__ Actx, const float* __restrict__ Bw,
    const float* __restrict__ bias, float* __restrict__ Yf)
{
    extern __shared__ char smem[];
    const uint32_t sbase = smem_u32(smem);
    const int col0 = blockIdx.x * 128;
    const int row0 = blockIdx.y * 128;

    const int tid  = threadIdx.x;
    const int wid  = tid >> 5;
    const int lane = tid & 31;
    const int wm   = wid >> 2;
    const int wn   = wid & 3;

    const int arl = lane & 15;
    const int acl = lane >> 4;
    const int brl = ((lane & 16) >> 1) + (lane & 7);
    const int bcl = (lane >> 3) & 1;

    float acc[4][4][4];
    #pragma unroll
    for (int mt = 0; mt < 4; mt++)
        #pragma unroll
        for (int nt = 0; nt < 4; nt++)
            #pragma unroll
            for (int u = 0; u < 4; u++) acc[mt][nt][u] = 0.f;

    auto load_stage = [&](int s, int c) {
        uint32_t stage = sbase + s * STAGE32;
        #pragma unroll
        for (int it = 0; it < 8; it++) {
            int u = tid + it * 256;          // 0..2047 16B units
            int t = u >> 10;                 // 0=A, 1=B
            int rem = u & 1023;
            int r = rem >> 3;
            int g = rem & 7;
            const float* src = t ? Bw : Actx;
            int grow = (t ? col0 : row0) + r;
            CP_ASYNC16(stage + (uint32_t)(t * TILE32) + cswz(r, g),
                       src + (size_t)grow * EMBED + c * KC + g * 4);
        }
    };

    load_stage(0, 0);
    CP_COMMIT();
    load_stage(1, 1);
    CP_COMMIT();

    int s = 0;
    for (int c = 0; c < NCH; c++) {
        if (c == NCH - 1) { CP_WAIT0(); } else { CP_WAIT1(); }
        __syncthreads();
        if (c + 2 < NCH) {
            int ns = s + 2;
            if (ns >= 3) ns -= 3;
            load_stage(ns, c + 2);
        }
        CP_COMMIT();

        const uint32_t st = sbase + s * STAGE32;
        #pragma unroll
        for (int kg = 0; kg < 4; kg++) {
            uint32_t av[4][4];
            #pragma unroll
            for (int mt = 0; mt < 4; mt++)
                ldsm4(av[mt], st + cswz(wm * 64 + mt * 16 + arl, 2 * kg + acl));
            #pragma unroll
            for (int np = 0; np < 2; np++) {
                uint32_t r4[4];
                ldsm4(r4, st + TILE32 +
                          cswz(wn * 32 + np * 16 + brl, 2 * kg + bcl));
                #pragma unroll
                for (int mt = 0; mt < 4; mt++) {
                    mma_tf32(acc[mt][2 * np], av[mt], r4[0], r4[1]);
                    mma_tf32(acc[mt][2 * np + 1], av[mt], r4[2], r4[3]);
                }
            }
        }
        s = (s == 2) ? 0 : s + 1;
    }

    #pragma unroll
    for (int mt = 0; mt < 4; mt++) {
        int r0 = row0 + wm * 64 + mt * 16 + (lane >> 2);
        #pragma unroll
        for (int nt = 0; nt < 4; nt++) {
            int mcol = col0 + wn * 32 + nt * 8 + 2 * (lane & 3);
            float b0 = bias[mcol], b1 = bias[mcol + 1];
            *(float2*)(Yf + (size_t)r0 * EMBED + mcol) =
                make_float2(acc[mt][nt][0] + b0, acc[mt][nt][1] + b1);
            *(float2*)(Yf + (size_t)(r0 + 8) * EMBED + mcol) =
                make_float2(acc[mt][nt][2] + b0, acc[mt][nt][3] + b1);
        }
    }
}

// ---------------------------------------------------------------------------
// Attention via mma.sync (96KB smem, 2 CTAs/SM). Context now written as fp32.
// ---------------------------------------------------------------------------
#define AT_QHI 0
#define AT_QLO 16384
#define AT_KHI 32768
#define AT_KLO 49152
#define AT_VHI 65536
#define AT_VLO 81920
#define AT_PHI 0
#define AT_PLO 32768
#define AT_MKW 98304
#define AT_SMEM (98304 + 32)

__device__ __forceinline__ uint32_t qswz(int r, int c) {
    return (uint32_t)(r * 128 + ((c ^ (r & 7)) * 16));
}
__device__ __forceinline__ uint32_t pswz(int r, int c) {
    return (uint32_t)(r * 256 + (((c & 8) | ((c & 7) ^ (r & 7))) * 16));
}

__global__ __launch_bounds__(256) void attn_mma(
    const bf16* __restrict__ qhi, const bf16* __restrict__ qlo,
    const bf16* __restrict__ khi, const bf16* __restrict__ klo,
    const bf16* __restrict__ vhi, const bf16* __restrict__ vlo,
    const unsigned char* __restrict__ mask, float* __restrict__ probs,
    float* __restrict__ ctx, int write_probs)
{
    extern __shared__ char smc[];
    const uint32_t sb = smem_u32(smc);

    const int c = blockIdx.x;
    const int h = blockIdx.y;
    const int tid = threadIdx.x;
    const int wid = tid >> 5;
    const int lane = tid & 31;
    const size_t base = (size_t)c * EMBED + h * DKK;

    {
        const bf16* srcs[6] = { qhi, qlo, khi, klo, vhi, vlo };
        #pragma unroll
        for (int t = 0; t < 6; t++) {
            #pragma unroll
            for (int it = 0; it < 4; it++) {
                int e = tid + it * 256;
                int r = e >> 3;
                int ch = e & 7;
                CP_ASYNC16(sb + (uint32_t)(t * 16384) + qswz(r, ch),
                           srcs[t] + (size_t)r * (CDIM * EMBED) + base + ch * 8);
            }
        }
        CP_COMMIT();
    }
    if (tid < 4) {
        uint32_t w = 0;
        for (int b = 0; b < 32; b++)
            if (mask[(size_t)(tid * 32 + b) * CDIM + c]) w |= (1u << b);
        *(uint32_t*)(smc + AT_MKW + tid * 4) = w;
    }
    CP_WAIT0();
    __syncthreads();

    const int i0 = wid * 16;

    float acc[16][4];
    #pragma unroll
    for (int nt = 0; nt < 16; nt++)
        #pragma unroll
        for (int u = 0; u < 4; u++) acc[nt][u] = 0.f;

    #pragma unroll
    for (int ks = 0; ks < 4; ks++) {
        uint32_t ah[4], al[4];
        {
            int rr = i0 + (lane & 15);
            int cc = 2 * ks + (lane >> 4);
            uint32_t ad = sb + AT_QHI + qswz(rr, cc);
            ldsm4(ah, ad);
            ldsm4(al, ad + 16384);
        }
        #pragma unroll
        for (int jg = 0; jg < 8; jg++) {
            int jr = jg * 16 + ((lane & 16) >> 1) + (lane & 7);
            int cc = 2 * ks + ((lane >> 3) & 1);
            uint32_t bd = sb + AT_KHI + qswz(jr, cc);
            uint32_t bh[4], bl[4];
            ldsm4(bh, bd);
            ldsm4(bl, bd + 16384);
            mma16816(acc[2 * jg], ah, bh[0], bh[1]);
            mma16816(acc[2 * jg], ah, bl[0], bl[1]);
            mma16816(acc[2 * jg], al, bh[0], bh[1]);
            mma16816(acc[2 * jg + 1], ah, bh[2], bh[3]);
            mma16816(acc[2 * jg + 1], ah, bl[2], bl[3]);
            mma16816(acc[2 * jg + 1], al, bh[2], bh[3]);
        }
    }

    __syncthreads();

    {
        uint32_t mw[4];
        #pragma unroll
        for (int u = 0; u < 4; u++) mw[u] = *(const uint32_t*)(smc + AT_MKW + u * 4);
        const int jb = (lane & 3) * 2;

        float mxl = -1e30f, mxh = -1e30f;
        #pragma unroll
        for (int nt = 0; nt < 16; nt++) {
            int j0 = nt * 8 + jb;
            bool m0 = (mw[j0 >> 5] >> (j0 & 31)) & 1;
            bool m1 = (mw[j0 >> 5] >> ((j0 + 1) & 31)) & 1;
            if (m0) { acc[nt][0] = -10000.f; acc[nt][2] = -10000.f; }
            if (m1) { acc[nt][1] = -10000.f; acc[nt][3] = -10000.f; }
            mxl = fmaxf(mxl, fmaxf(acc[nt][0], acc[nt][1]));
            mxh = fmaxf(mxh, fmaxf(acc[nt][2], acc[nt][3]));
        }
        #pragma unroll
        for (int o = 1; o <= 2; o <<= 1) {
            mxl = fmaxf(mxl, __shfl_xor_sync(0xffffffffu, mxl, o));
            mxh = fmaxf(mxh, __shfl_xor_sync(0xffffffffu, mxh, o));
        }
        float sl = 0.f, sh = 0.f;
        #pragma unroll
        for (int nt = 0; nt < 16; nt++) {
            acc[nt][0] = __expf(acc[nt][0] - mxl);
            acc[nt][1] = __expf(acc[nt][1] - mxl);
            acc[nt][2] = __expf(acc[nt][2] - mxh);
            acc[nt][3] = __expf(acc[nt][3] - mxh);
            sl += acc[nt][0] + acc[nt][1];
            sh += acc[nt][2] + acc[nt][3];
        }
        #pragma unroll
        for (int o = 1; o <= 2; o <<= 1) {
            sl += __shfl_xor_sync(0xffffffffu, sl, o);
            sh += __shfl_xor_sync(0xffffffffu, sh, o);
        }
        float il = 1.f / sl, ih = 1.f / sh;

        const int rl = i0 + (lane >> 2);
        #pragma unroll
        for (int nt = 0; nt < 16; nt++) {
            float p0 = acc[nt][0] * il;
            float p1 = acc[nt][1] * il;
            float p2 = acc[nt][2] * ih;
            float p3 = acc[nt][3] * ih;
            bf16 h0 = __float2bfloat16(p0), h1 = __float2bfloat16(p1);
            bf16 h2 = __float2bfloat16(p2), h3 = __float2bfloat16(p3);
            uint32_t a0 = pswz(rl, nt) + (uint32_t)(jb * 2);
            uint32_t a1 = pswz(rl + 8, nt) + (uint32_t)(jb * 2);
            *(bf162*)(smc + AT_PHI + a0) = bf162(h0, h1);
            *(bf162*)(smc + AT_PHI + a1) = bf162(h2, h3);
            bf16 l0 = __float2bfloat16(p0 - __bfloat162float(h0));
            bf16 l1 = __float2bfloat16(p1 - __bfloat162float(h1));
            bf16 l2 = __float2bfloat16(p2 - __bfloat162float(h2));
            bf16 l3 = __float2bfloat16(p3 - __bfloat162float(h3));
            *(bf162*)(smc + AT_PLO + a0) = bf162(l0, l1);
            *(bf162*)(smc + AT_PLO + a1) = bf162(l2, l3);
        }
    }
    __syncthreads();

    if (write_probs) {
        const size_t pb = ((size_t)(h * CDIM + c) * RDIM) * RDIM;
        #pragma unroll
        for (int it = 0; it < 16; it++) {
            int e = tid + it * 256;
            int r = e >> 5;
            int s2 = e & 31;
            uint32_t pa = pswz(r, s2 >> 1) + (uint32_t)((s2 & 1) * 8);
            uint2 uh = *(const uint2*)(smc + AT_PHI + pa);
            uint2 ul = *(const uint2*)(smc + AT_PLO + pa);
            bf162 h0 = *(bf162*)&uh.x, h1 = *(bf162*)&uh.y;
            bf162 l0 = *(bf162*)&ul.x, l1 = *(bf162*)&ul.y;
            float4 o;
            o.x = __bfloat162float(h0.x) + __bfloat162float(l0.x);
            o.y = __bfloat162float(h0.y) + __bfloat162float(l0.y);
            o.z = __bfloat162float(h1.x) + __bfloat162float(l1.x);
            o.w = __bfloat162float(h1.y) + __bfloat162float(l1.y);
            *(float4*)(probs + pb + (size_t)r * RDIM + s2 * 4) = o;
        }
    }

    float acc2[8][4];
    #pragma unroll
    for (int nt = 0; nt < 8; nt++)
        #pragma unroll
        for (int u = 0; u < 4; u++) acc2[nt][u] = 0.f;

    #pragma unroll
    for (int j16 = 0; j16 < 8; j16++) {
        uint32_t ph4[4], pl4[4];
        {
            int rr = i0 + (lane & 15);
            int cc = 2 * j16 + (lane >> 4);
            uint32_t ad = sb + AT_PHI + pswz(rr, cc);
            ldsm4(ph4, ad);
            ldsm4(pl4, ad + 32768);
        }
        #pragma unroll
        for (int dg = 0; dg < 4; dg++) {
            int jr = j16 * 16 + (lane & 7) + ((lane >> 3) & 1) * 8;
            int cc = 2 * dg + (lane >> 4);
            uint32_t vd = sb + AT_VHI + qswz(jr, cc);
            uint32_t vh4[4], vl4[4];
            ldsm4t(vh4, vd);
            ldsm4t(vl4, vd + 16384);
            mma16816(acc2[2 * dg], ph4, vh4[0], vh4[1]);
            mma16816(acc2[2 * dg], ph4, vl4[0], vl4[1]);
            mma16816(acc2[2 * dg], pl4, vh4[0], vh4[1]);
            mma16816(acc2[2 * dg + 1], ph4, vh4[2], vh4[3]);
            mma16816(acc2[2 * dg + 1], ph4, vl4[2], vl4[3]);
            mma16816(acc2[2 * dg + 1], pl4, vh4[2], vh4[3]);
        }
    }

    {
        const int r0 = i0 + (lane >> 2);
        #pragma unroll
        for (int nt = 0; nt < 8; nt++) {
            int d0 = nt * 8 + (lane & 3) * 2;
            size_t g0 = (size_t)r0 * (CDIM * EMBED) + base + d0;
            size_t g1 = (size_t)(r0 + 8) * (CDIM * EMBED) + base + d0;
            *(float2*)(ctx + g0) = make_float2(acc2[nt][0], acc2[nt][1]);
            *(float2*)(ctx + g1) = make_float2(acc2[nt][2], acc2[nt][3]);
        }
    }
}

// ---------------------------------------------------------------------------
extern "C" void kernel_launch(void* const* d_in, const int* in_sizes, int n_in,
                              void* d_out, int out_size)
{
    const float* x  = (const float*)d_in[0];
    const unsigned char* mask = (const unsigned char*)d_in[1];
    const float* Wq = (const float*)d_in[2];
    const float* bq = (const float*)d_in[3];
    const float* Wk = (const float*)d_in[4];
    const float* bk = (const float*)d_in[5];
    const float* Wv = (const float*)d_in[6];
    const float* bv = (const float*)d_in[7];
    const float* Wo = (const float*)d_in[8];
    const float* bo = (const float*)d_in[9];
    float* out = (float*)d_out;

    bf16 *xhi, *xlo, *qhi, *qlo, *khi, *klo, *vhi, *vlo, *whi, *wlo;
    float* ctx;
    cudaGetSymbolAddress((void**)&xhi, g_xhi);
    cudaGetSymbolAddress((void**)&xlo, g_xlo);
    cudaGetSymbolAddress((void**)&qhi, g_qhi);
    cudaGetSymbolAddress((void**)&qlo, g_qlo);
    cudaGetSymbolAddress((void**)&khi, g_khi);
    cudaGetSymbolAddress((void**)&klo, g_klo);
    cudaGetSymbolAddress((void**)&vhi, g_vhi);
    cudaGetSymbolAddress((void**)&vlo, g_vlo);
    cudaGetSymbolAddress((void**)&whi, g_whi);
    cudaGetSymbolAddress((void**)&wlo, g_wlo);
    cudaGetSymbolAddress((void**)&ctx, g_ctx);

    const long long out_elems = (long long)NTOK * EMBED;
    const long long probs_elems = (long long)HEADS * CDIM * RDIM * RDIM;
    int write_probs = ((long long)out_size >= out_elems + probs_elems) ? 1 : 0;
    float* probs = write_probs ? (out + out_elems) : nullptr;

    cudaFuncSetAttribute(mma_gemm_qkv, cudaFuncAttributeMaxDynamicSharedMemorySize, GSMEM);
    cudaFuncSetAttribute(mma_gemm_out, cudaFuncAttributeMaxDynamicSharedMemorySize, GSMEM);
    cudaFuncSetAttribute(attn_mma, cudaFuncAttributeMaxDynamicSharedMemorySize, AT_SMEM);

    const size_t WSZ = (size_t)EMBED * EMBED;
    const int xn4 = (int)(((size_t)NTOK * EMBED) / 4);
    const int wn4 = (int)(WSZ / 4);

    split_kernel<<<(xn4 + 255) / 256, 256>>>((const float4*)x, xhi, xlo, xn4);
    {
        dim3 wgrid((wn4 + 255) / 256, 3);
        split_w_kernel<<<wgrid, 256>>>((const float4*)Wq, (const float4*)Wk,
                                       (const float4*)Wv, whi, wlo, wn4);
    }

    dim3 qkvgrid(18, NTOK / 128);          // (18, 256)
    mma_gemm_qkv<<<qkvgrid, 256, GSMEM>>>(xhi, xlo, whi, wlo,
                                          bq, bk, bv,
                                          qhi, qlo, khi, klo, vhi, vlo);

    dim3 agrid(CDIM, HEADS);
    attn_mma<<<agrid, 256, AT_SMEM>>>(qhi, qlo, khi, klo, vhi, vlo,
                                      mask, probs, ctx, write_probs);

    dim3 ogrid(EMBED / 128, NTOK / 128);   // (6, 256)
    mma_gemm_out<<<ogrid, 256, GSMEM>>>(ctx, Wo, bo, out);
}

// round 16
// speedup vs baseline: 1.3747x; 1.0663x over previous
#include <cuda_runtime.h>
#include <cuda_bf16.h>
#include <cstdint>

#define EMBED 768
#define HEADS 12
#define DKK   64
#define RDIM  128
#define CDIM  256
#define NTOK  (RDIM * CDIM)   // 32768

typedef __nv_bfloat16 bf16;
typedef __nv_bfloat162 bf162;

__device__ bf16 g_xhi[(size_t)NTOK * EMBED];
__device__ bf16 g_xlo[(size_t)NTOK * EMBED];
__device__ float g_xtf[(size_t)NTOK * EMBED];       // x rounded to tf32
__device__ bf16 g_qhi[(size_t)NTOK * EMBED];
__device__ bf16 g_qlo[(size_t)NTOK * EMBED];
__device__ bf16 g_khi[(size_t)NTOK * EMBED];
__device__ bf16 g_klo[(size_t)NTOK * EMBED];
__device__ bf16 g_vhi[(size_t)NTOK * EMBED];
__device__ bf16 g_vlo[(size_t)NTOK * EMBED];
__device__ bf16 g_whi[2 * (size_t)EMBED * EMBED];   // Wq, Wk bf16 splits
__device__ bf16 g_wlo[2 * (size_t)EMBED * EMBED];
__device__ float g_wvtf[(size_t)EMBED * EMBED];     // Wv rounded to tf32
__device__ float g_wotf[(size_t)EMBED * EMBED];     // Wo rounded to tf32
__device__ float g_ctx[(size_t)NTOK * EMBED];       // fp32 (tf32-rounded) context

__device__ __forceinline__ uint32_t smem_u32(const void* p) {
    uint32_t a;
    asm("{ .reg .u64 t; cvta.to.shared.u64 t, %1; cvt.u32.u64 %0, t; }"
        : "=r"(a) : "l"(p));
    return a;
}

__device__ __forceinline__ float rtf(float x) {
    uint32_t u;
    asm("cvt.rna.tf32.f32 %0, %1;" : "=r"(u) : "f"(x));
    return __uint_as_float(u);
}

__device__ __forceinline__ void ldsm4(uint32_t (&r)[4], uint32_t addr) {
    asm volatile("ldmatrix.sync.aligned.m8n8.x4.shared.b16 {%0,%1,%2,%3}, [%4];"
                 : "=r"(r[0]), "=r"(r[1]), "=r"(r[2]), "=r"(r[3]) : "r"(addr));
}

__device__ __forceinline__ void ldsm4t(uint32_t (&r)[4], uint32_t addr) {
    asm volatile("ldmatrix.sync.aligned.m8n8.x4.trans.shared.b16 {%0,%1,%2,%3}, [%4];"
                 : "=r"(r[0]), "=r"(r[1]), "=r"(r[2]), "=r"(r[3]) : "r"(addr));
}

__device__ __forceinline__ void mma16816(float (&c)[4], const uint32_t (&a)[4],
                                         uint32_t b0, uint32_t b1) {
    asm volatile(
        "mma.sync.aligned.m16n8k16.row.col.f32.bf16.bf16.f32 "
        "{%0,%1,%2,%3}, {%4,%5,%6,%7}, {%8,%9}, {%0,%1,%2,%3};"
        : "+f"(c[0]), "+f"(c[1]), "+f"(c[2]), "+f"(c[3])
        : "r"(a[0]), "r"(a[1]), "r"(a[2]), "r"(a[3]), "r"(b0), "r"(b1));
}

__device__ __forceinline__ void mma_tf32(float (&c)[4], const uint32_t (&a)[4],
                                         uint32_t b0, uint32_t b1) {
    asm volatile(
        "mma.sync.aligned.m16n8k8.row.col.f32.tf32.tf32.f32 "
        "{%0,%1,%2,%3}, {%4,%5,%6,%7}, {%8,%9}, {%0,%1,%2,%3};"
        : "+f"(c[0]), "+f"(c[1]), "+f"(c[2]), "+f"(c[3])
        : "r"(a[0]), "r"(a[1]), "r"(a[2]), "r"(a[3]), "r"(b0), "r"(b1));
}

#define CP_ASYNC16(dst, src) \
    asm volatile("cp.async.cg.shared.global [%0], [%1], 16;" \
                 :: "r"(dst), "l"(src))
#define CP_COMMIT() asm volatile("cp.async.commit_group;" ::: "memory")
#define CP_WAIT0()  asm volatile("cp.async.wait_group 0;" ::: "memory")
#define CP_WAIT1()  asm volatile("cp.async.wait_group 1;" ::: "memory")

// ---------------------------------------------------------------------------
__device__ __forceinline__ void split4(const float4 v, bf162* hp, bf162* lp) {
    bf16 h0 = __float2bfloat16(v.x);
    bf16 h1 = __float2bfloat16(v.y);
    bf16 h2 = __float2bfloat16(v.z);
    bf16 h3 = __float2bfloat16(v.w);
    bf16 l0 = __float2bfloat16(v.x - __bfloat162float(h0));
    bf16 l1 = __float2bfloat16(v.y - __bfloat162float(h1));
    bf16 l2 = __float2bfloat16(v.z - __bfloat162float(h2));
    bf16 l3 = __float2bfloat16(v.w - __bfloat162float(h3));
    hp[0] = bf162(h0, h1);
    hp[1] = bf162(h2, h3);
    lp[0] = bf162(l0, l1);
    lp[1] = bf162(l2, l3);
}

// x: bf16 hi/lo splits + rounded-tf32 copy
__global__ __launch_bounds__(256) void split_x_kernel(
    const float4* __restrict__ src, bf16* __restrict__ hi,
    bf16* __restrict__ lo, float4* __restrict__ tf, int n4)
{
    int i = blockIdx.x * blockDim.x + threadIdx.x;
    if (i >= n4) return;
    float4 v = src[i];
    split4(v, (bf162*)(hi + (size_t)i * 4), (bf162*)(lo + (size_t)i * 4));
    tf[i] = make_float4(rtf(v.x), rtf(v.y), rtf(v.z), rtf(v.w));
}

// Wq, Wk -> bf16 splits
__global__ __launch_bounds__(256) void split_w_kernel(
    const float4* __restrict__ w0, const float4* __restrict__ w1,
    bf16* __restrict__ hi, bf16* __restrict__ lo, int n4)
{
    int i = blockIdx.x * blockDim.x + threadIdx.x;
    if (i >= n4) return;
    const float4* src = (blockIdx.y == 0) ? w0 : w1;
    size_t o = (size_t)blockIdx.y * n4 * 4 + (size_t)i * 4;
    split4(src[i], (bf162*)(hi + o), (bf162*)(lo + o));
}

// Wv, Wo -> rounded tf32
__global__ __launch_bounds__(256) void round_w_kernel(
    const float4* __restrict__ w0, const float4* __restrict__ w1,
    float4* __restrict__ o0, float4* __restrict__ o1, int n4)
{
    int i = blockIdx.x * blockDim.x + threadIdx.x;
    if (i >= n4) return;
    const float4* src = (blockIdx.y == 0) ? w0 : w1;
    float4* dst = (blockIdx.y == 0) ? o0 : o1;
    float4 v = src[i];
    dst[i] = make_float4(rtf(v.x), rtf(v.y), rtf(v.z), rtf(v.w));
}

// ---------------------------------------------------------------------------
// GEMM config (both paths): CTA 128x128, 8 warps, K-chunk 32, 3-stage pipeline.
// bf16 path: 64B swizzled rows (4 tiles/stage).  tf32 path: 128B swizzled rows
// (2 tiles/stage).  Both stages = 32KB -> 96KB smem, 2 CTAs/SM.
// ---------------------------------------------------------------------------
#define KC      32
#define NCH     (EMBED / KC)          // 24
#define TILEB   (128 * 64)            // 8192 B
#define STAGEB  (4 * TILEB)           // 32768
#define GSMEM   (3 * STAGEB)          // 98304
#define TILE32  16384
#define STAGE32 32768

__device__ __forceinline__ uint32_t gswz(int r, int c) {
    return (uint32_t)(r * 64 + ((c ^ ((r >> 1) & 3)) << 4));
}
__device__ __forceinline__ uint32_t cswz(int r, int c) {
    return (uint32_t)(r * 128 + ((c ^ (r & 7)) << 4));
}

__device__ __forceinline__ void gemm_mainloop(
    const bf16* __restrict__ Ahi, const bf16* __restrict__ Alo,
    const bf16* __restrict__ Bhi, const bf16* __restrict__ Blo,
    int row0, int col0, uint32_t sbase, float (&acc)[4][4][4])
{
    const int tid  = threadIdx.x;
    const int wid  = tid >> 5;
    const int lane = tid & 31;
    const int wm   = wid >> 2;
    const int wn   = wid & 3;

    const int arl = lane & 15;
    const int acl = lane >> 4;
    const int brl = ((lane & 16) >> 1) + (lane & 7);
    const int bcl = (lane >> 3) & 1;

    auto load_stage = [&](int s, int c) {
        uint32_t stage = sbase + s * STAGEB;
        #pragma unroll
        for (int it = 0; it < 8; it++) {
            int u = tid + it * 256;
            int t = u >> 9;
            int rem = u & 511;
            int r = rem >> 2;
            int g = rem & 3;
            const bf16* src;
            int grow;
            if (t == 0)      { src = Ahi; grow = row0 + r; }
            else if (t == 1) { src = Alo; grow = row0 + r; }
            else if (t == 2) { src = Bhi; grow = col0 + r; }
            else             { src = Blo; grow = col0 + r; }
            CP_ASYNC16(stage + (uint32_t)(t * TILEB) + gswz(r, g),
                       src + (size_t)grow * EMBED + c * KC + g * 8);
        }
    };

    load_stage(0, 0);
    CP_COMMIT();
    load_stage(1, 1);
    CP_COMMIT();

    int s = 0;
    for (int c = 0; c < NCH; c++) {
        if (c == NCH - 1) { CP_WAIT0(); } else { CP_WAIT1(); }
        __syncthreads();
        if (c + 2 < NCH) {
            int ns = s + 2;
            if (ns >= 3) ns -= 3;
            load_stage(ns, c + 2);
        }
        CP_COMMIT();

        const uint32_t st = sbase + s * STAGEB;
        #pragma unroll
        for (int ks = 0; ks < 2; ks++) {
            uint32_t ah[4][4], al[4][4];
            uint32_t bh[4][2], bl[4][2];
            #pragma unroll
            for (int mt = 0; mt < 4; mt++) {
                uint32_t ra = st + gswz(wm * 64 + mt * 16 + arl, 2 * ks + acl);
                ldsm4(ah[mt], ra);
                ldsm4(al[mt], ra + TILEB);
            }
            #pragma unroll
            for (int np = 0; np < 2; np++) {
                uint32_t rb = st + 2 * TILEB +
                              gswz(wn * 32 + np * 16 + brl, 2 * ks + bcl);
                uint32_t rh[4], rl[4];
                ldsm4(rh, rb);
                ldsm4(rl, rb + TILEB);
                bh[2 * np][0] = rh[0]; bh[2 * np][1] = rh[1];
                bh[2 * np + 1][0] = rh[2]; bh[2 * np + 1][1] = rh[3];
                bl[2 * np][0] = rl[0]; bl[2 * np][1] = rl[1];
                bl[2 * np + 1][0] = rl[2]; bl[2 * np + 1][1] = rl[3];
            }
            #pragma unroll
            for (int mt = 0; mt < 4; mt++)
                #pragma unroll
                for (int nt = 0; nt < 4; nt++) {
                    mma16816(acc[mt][nt], ah[mt], bh[nt][0], bh[nt][1]);
                    mma16816(acc[mt][nt], ah[mt], bl[nt][0], bl[nt][1]);
                    mma16816(acc[mt][nt], al[mt], bh[nt][0], bh[nt][1]);
                }
        }
        s = (s == 2) ? 0 : s + 1;
    }
}

// Single-pass tf32 mainloop (operands pre-rounded to tf32 -> exact in hardware)
__device__ __forceinline__ void gemm_mainloop_tf32(
    const float* __restrict__ A, const float* __restrict__ B,
    int row0, int col0, uint32_t sbase, float (&acc)[4][4][4])
{
    const int tid  = threadIdx.x;
    const int wid  = tid >> 5;
    const int lane = tid & 31;
    const int wm   = wid >> 2;
    const int wn   = wid & 3;

    const int arl = lane & 15;
    const int acl = lane >> 4;
    const int brl = ((lane & 16) >> 1) + (lane & 7);
    const int bcl = (lane >> 3) & 1;

    auto load_stage = [&](int s, int c) {
        uint32_t stage = sbase + s * STAGE32;
        #pragma unroll
        for (int it = 0; it < 8; it++) {
            int u = tid + it * 256;
            int t = u >> 10;
            int rem = u & 1023;
            int r = rem >> 3;
            int g = rem & 7;
            const float* src = t ? B : A;
            int grow = (t ? col0 : row0) + r;
            CP_ASYNC16(stage + (uint32_t)(t * TILE32) + cswz(r, g),
                       src + (size_t)grow * EMBED + c * KC + g * 4);
        }
    };

    load_stage(0, 0);
    CP_COMMIT();
    load_stage(1, 1);
    CP_COMMIT();

    int s = 0;
    for (int c = 0; c < NCH; c++) {
        if (c == NCH - 1) { CP_WAIT0(); } else { CP_WAIT1(); }
        __syncthreads();
        if (c + 2 < NCH) {
            int ns = s + 2;
            if (ns >= 3) ns -= 3;
            load_stage(ns, c + 2);
        }
        CP_COMMIT();

        const uint32_t st = sbase + s * STAGE32;
        #pragma unroll
        for (int kg = 0; kg < 4; kg++) {
            uint32_t av[4][4];
            #pragma unroll
            for (int mt = 0; mt < 4; mt++)
                ldsm4(av[mt], st + cswz(wm * 64 + mt * 16 + arl, 2 * kg + acl));
            #pragma unroll
            for (int np = 0; np < 2; np++) {
                uint32_t r4[4];
                ldsm4(r4, st + TILE32 +
                          cswz(wn * 32 + np * 16 + brl, 2 * kg + bcl));
                #pragma unroll
                for (int mt = 0; mt < 4; mt++) {
                    mma_tf32(acc[mt][2 * np], av[mt], r4[0], r4[1]);
                    mma_tf32(acc[mt][2 * np + 1], av[mt], r4[2], r4[3]);
                }
            }
        }
        s = (s == 2) ? 0 : s + 1;
    }
}

// Fused QKV GEMM. grid (18, 256): x<12 -> bf16 Q/K path; x>=12 -> tf32 V path.
__global__ __launch_bounds__(256) void mma_gemm_qkv(
    const bf16* __restrict__ Xhi, const bf16* __restrict__ Xlo,
    const bf16* __restrict__ Whi, const bf16* __restrict__ Wlo,
    const float* __restrict__ Xtf, const float* __restrict__ Wvtf,
    const float* __restrict__ bq, const float* __restrict__ bk,
    const float* __restrict__ bv,
    bf16* __restrict__ qhi, bf16* __restrict__ qlo,
    bf16* __restrict__ khi, bf16* __restrict__ klo,
    bf16* __restrict__ vhi, bf16* __restrict__ vlo)
{
    extern __shared__ char smem[];
    const uint32_t sbase = smem_u32(smem);
    const int row0 = blockIdx.y * 128;

    const int lane = threadIdx.x & 31;
    const int wid  = threadIdx.x >> 5;
    const int wm   = wid >> 2;
    const int wn   = wid & 3;

    float acc[4][4][4];
    #pragma unroll
    for (int mt = 0; mt < 4; mt++)
        #pragma unroll
        for (int nt = 0; nt < 4; nt++)
            #pragma unroll
            for (int u = 0; u < 4; u++) acc[mt][nt][u] = 0.f;

    const float* bias;
    bf16* Yhi;
    bf16* Ylo;
    float scale;
    int col0;

    if (blockIdx.x < 12) {
        const int wsel = blockIdx.x / 6;          // 0=Q, 1=K
        col0 = (blockIdx.x % 6) * 128;
        const size_t WSZ = (size_t)EMBED * EMBED;
        gemm_mainloop(Xhi, Xlo, Whi + (size_t)wsel * WSZ, Wlo + (size_t)wsel * WSZ,
                      row0, col0, sbase, acc);
        bias = wsel ? bk : bq;
        Yhi = wsel ? khi : qhi;
        Ylo = wsel ? klo : qlo;
        scale = wsel ? 1.f : 0.125f;
    } else {
        col0 = (blockIdx.x - 12) * 128;
        gemm_mainloop_tf32(Xtf, Wvtf, row0, col0, sbase, acc);
        bias = bv;
        Yhi = vhi;
        Ylo = vlo;
        scale = 1.f;
    }

    #pragma unroll
    for (int mt = 0; mt < 4; mt++) {
        int r0 = row0 + wm * 64 + mt * 16 + (lane >> 2);
        #pragma unroll
        for (int nt = 0; nt < 4; nt++) {
            int mcol = col0 + wn * 32 + nt * 8 + 2 * (lane & 3);
            float b0 = bias[mcol], b1 = bias[mcol + 1];
            float o0 = (acc[mt][nt][0] + b0) * scale;
            float o1 = (acc[mt][nt][1] + b1) * scale;
            float o2 = (acc[mt][nt][2] + b0) * scale;
            float o3 = (acc[mt][nt][3] + b1) * scale;
            bf16 h0 = __float2bfloat16(o0), h1 = __float2bfloat16(o1);
            bf16 h2 = __float2bfloat16(o2), h3 = __float2bfloat16(o3);
            *(bf162*)(Yhi + (size_t)r0 * EMBED + mcol) = bf162(h0, h1);
            *(bf162*)(Yhi + (size_t)(r0 + 8) * EMBED + mcol) = bf162(h2, h3);
            bf16 l0 = __float2bfloat16(o0 - __bfloat162float(h0));
            bf16 l1 = __float2bfloat16(o1 - __bfloat162float(h1));
            bf16 l2 = __float2bfloat16(o2 - __bfloat162float(h2));
            bf16 l3 = __float2bfloat16(o3 - __bfloat162float(h3));
            *(bf162*)(Ylo + (size_t)r0 * EMBED + mcol) = bf162(l0, l1);
            *(bf162*)(Ylo + (size_t)(r0 + 8) * EMBED + mcol) = bf162(l2, l3);
        }
    }
}

// Output-projection GEMM (tf32, operands pre-rounded): grid (6, 256), f32 out.
__global__ __launch_bounds__(256) void mma_gemm_out(
    const float* __restrict__ Actx, const float* __restrict__ Bw,
    const float* __restrict__ bias, float* __restrict__ Yf)
{
    extern __shared__ char smem[];
    const uint32_t sbase = smem_u32(smem);
    const int col0 = blockIdx.x * 128;
    const int row0 = blockIdx.y * 128;

    const int lane = threadIdx.x & 31;
    const int wid  = threadIdx.x >> 5;
    const int wm   = wid >> 2;
    const int wn   = wid & 3;

    float acc[4][4][4];
    #pragma unroll
    for (int mt = 0; mt < 4; mt++)
        #pragma unroll
        for (int nt = 0; nt < 4; nt++)
            #pragma unroll
            for (int u = 0; u < 4; u++) acc[mt][nt][u] = 0.f;

    gemm_mainloop_tf32(Actx, Bw, row0, col0, sbase, acc);

    #pragma unroll
    for (int mt = 0; mt < 4; mt++) {
        int r0 = row0 + wm * 64 + mt * 16 + (lane >> 2);
        #pragma unroll
        for (int nt = 0; nt < 4; nt++) {
            int mcol = col0 + wn * 32 + nt * 8 + 2 * (lane & 3);
            float b0 = bias[mcol], b1 = bias[mcol + 1];
            *(float2*)(Yf + (size_t)r0 * EMBED + mcol) =
                make_float2(acc[mt][nt][0] + b0, acc[mt][nt][1] + b1);
            *(float2*)(Yf + (size_t)(r0 + 8) * EMBED + mcol) =
                make_float2(acc[mt][nt][2] + b0, acc[mt][nt][3] + b1);
        }
    }
}

// ---------------------------------------------------------------------------
// Attention via mma.sync (96KB smem, 2 CTAs/SM). Context stored tf32-rounded.
// ---------------------------------------------------------------------------
#define AT_QHI 0
#define AT_QLO 16384
#define AT_KHI 32768
#define AT_KLO 49152
#define AT_VHI 65536
#define AT_VLO 81920
#define AT_PHI 0
#define AT_PLO 32768
#define AT_MKW 98304
#define AT_SMEM (98304 + 32)

__device__ __forceinline__ uint32_t qswz(int r, int c) {
    return (uint32_t)(r * 128 + ((c ^ (r & 7)) * 16));
}
__device__ __forceinline__ uint32_t pswz(int r, int c) {
    return (uint32_t)(r * 256 + (((c & 8) | ((c & 7) ^ (r & 7))) * 16));
}

__global__ __launch_bounds__(256) void attn_mma(
    const bf16* __restrict__ qhi, const bf16* __restrict__ qlo,
    const bf16* __restrict__ khi, const bf16* __restrict__ klo,
    const bf16* __restrict__ vhi, const bf16* __restrict__ vlo,
    const unsigned char* __restrict__ mask, float* __restrict__ probs,
    float* __restrict__ ctx, int write_probs)
{
    extern __shared__ char smc[];
    const uint32_t sb = smem_u32(smc);

    const int c = blockIdx.x;
    const int h = blockIdx.y;
    const int tid = threadIdx.x;
    const int wid = tid >> 5;
    const int lane = tid & 31;
    const size_t base = (size_t)c * EMBED + h * DKK;

    {
        const bf16* srcs[6] = { qhi, qlo, khi, klo, vhi, vlo };
        #pragma unroll
        for (int t = 0; t < 6; t++) {
            #pragma unroll
            for (int it = 0; it < 4; it++) {
                int e = tid + it * 256;
                int r = e >> 3;
                int ch = e & 7;
                CP_ASYNC16(sb + (uint32_t)(t * 16384) + qswz(r, ch),
                           srcs[t] + (size_t)r * (CDIM * EMBED) + base + ch * 8);
            }
        }
        CP_COMMIT();
    }
    if (tid < 4) {
        uint32_t w = 0;
        for (int b = 0; b < 32; b++)
            if (mask[(size_t)(tid * 32 + b) * CDIM + c]) w |= (1u << b);
        *(uint32_t*)(smc + AT_MKW + tid * 4) = w;
    }
    CP_WAIT0();
    __syncthreads();

    const int i0 = wid * 16;

    float acc[16][4];
    #pragma unroll
    for (int nt = 0; nt < 16; nt++)
        #pragma unroll
        for (int u = 0; u < 4; u++) acc[nt][u] = 0.f;

    #pragma unroll
    for (int ks = 0; ks < 4; ks++) {
        uint32_t ah[4], al[4];
        {
            int rr = i0 + (lane & 15);
            int cc = 2 * ks + (lane >> 4);
            uint32_t ad = sb + AT_QHI + qswz(rr, cc);
            ldsm4(ah, ad);
            ldsm4(al, ad + 16384);
        }
        #pragma unroll
        for (int jg = 0; jg < 8; jg++) {
            int jr = jg * 16 + ((lane & 16) >> 1) + (lane & 7);
            int cc = 2 * ks + ((lane >> 3) & 1);
            uint32_t bd = sb + AT_KHI + qswz(jr, cc);
            uint32_t bh[4], bl[4];
            ldsm4(bh, bd);
            ldsm4(bl, bd + 16384);
            mma16816(acc[2 * jg], ah, bh[0], bh[1]);
            mma16816(acc[2 * jg], ah, bl[0], bl[1]);
            mma16816(acc[2 * jg], al, bh[0], bh[1]);
            mma16816(acc[2 * jg + 1], ah, bh[2], bh[3]);
            mma16816(acc[2 * jg + 1], ah, bl[2], bl[3]);
            mma16816(acc[2 * jg + 1], al, bh[2], bh[3]);
        }
    }

    __syncthreads();

    {
        uint32_t mw[4];
        #pragma unroll
        for (int u = 0; u < 4; u++) mw[u] = *(const uint32_t*)(smc + AT_MKW + u * 4);
        const int jb = (lane & 3) * 2;

        float mxl = -1e30f, mxh = -1e30f;
        #pragma unroll
        for (int nt = 0; nt < 16; nt++) {
            int j0 = nt * 8 + jb;
            bool m0 = (mw[j0 >> 5] >> (j0 & 31)) & 1;
            bool m1 = (mw[j0 >> 5] >> ((j0 + 1) & 31)) & 1;
            if (m0) { acc[nt][0] = -10000.f; acc[nt][2] = -10000.f; }
            if (m1) { acc[nt][1] = -10000.f; acc[nt][3] = -10000.f; }
            mxl = fmaxf(mxl, fmaxf(acc[nt][0], acc[nt][1]));
            mxh = fmaxf(mxh, fmaxf(acc[nt][2], acc[nt][3]));
        }
        #pragma unroll
        for (int o = 1; o <= 2; o <<= 1) {
            mxl = fmaxf(mxl, __shfl_xor_sync(0xffffffffu, mxl, o));
            mxh = fmaxf(mxh, __shfl_xor_sync(0xffffffffu, mxh, o));
        }
        float sl = 0.f, sh = 0.f;
        #pragma unroll
        for (int nt = 0; nt < 16; nt++) {
            acc[nt][0] = __expf(acc[nt][0] - mxl);
            acc[nt][1] = __expf(acc[nt][1] - mxl);
            acc[nt][2] = __expf(acc[nt][2] - mxh);
            acc[nt][3] = __expf(acc[nt][3] - mxh);
            sl += acc[nt][0] + acc[nt][1];
            sh += acc[nt][2] + acc[nt][3];
        }
        #pragma unroll
        for (int o = 1; o <= 2; o <<= 1) {
            sl += __shfl_xor_sync(0xffffffffu, sl, o);
            sh += __shfl_xor_sync(0xffffffffu, sh, o);
        }
        float il = 1.f / sl, ih = 1.f / sh;

        const int rl = i0 + (lane >> 2);
        #pragma unroll
        for (int nt = 0; nt < 16; nt++) {
            float p0 = acc[nt][0] * il;
            float p1 = acc[nt][1] * il;
            float p2 = acc[nt][2] * ih;
            float p3 = acc[nt][3] * ih;
            bf16 h0 = __float2bfloat16(p0), h1 = __float2bfloat16(p1);
            bf16 h2 = __float2bfloat16(p2), h3 = __float2bfloat16(p3);
            uint32_t a0 = pswz(rl, nt) + (uint32_t)(jb * 2);
            uint32_t a1 = pswz(rl + 8, nt) + (uint32_t)(jb * 2);
            *(bf162*)(smc + AT_PHI + a0) = bf162(h0, h1);
            *(bf162*)(smc + AT_PHI + a1) = bf162(h2, h3);
            bf16 l0 = __float2bfloat16(p0 - __bfloat162float(h0));
            bf16 l1 = __float2bfloat16(p1 - __bfloat162float(h1));
            bf16 l2 = __float2bfloat16(p2 - __bfloat162float(h2));
            bf16 l3 = __float2bfloat16(p3 - __bfloat162float(h3));
            *(bf162*)(smc + AT_PLO + a0) = bf162(l0, l1);
            *(bf162*)(smc + AT_PLO + a1) = bf162(l2, l3);
        }
    }
    __syncthreads();

    if (write_probs) {
        const size_t pb = ((size_t)(h * CDIM + c) * RDIM) * RDIM;
        #pragma unroll
        for (int it = 0; it < 16; it++) {
            int e = tid + it * 256;
            int r = e >> 5;
            int s2 = e & 31;
            uint32_t pa = pswz(r, s2 >> 1) + (uint32_t)((s2 & 1) * 8);
            uint2 uh = *(const uint2*)(smc + AT_PHI + pa);
            uint2 ul = *(const uint2*)(smc + AT_PLO + pa);
            bf162 h0 = *(bf162*)&uh.x, h1 = *(bf162*)&uh.y;
            bf162 l0 = *(bf162*)&ul.x, l1 = *(bf162*)&ul.y;
            float4 o;
            o.x = __bfloat162float(h0.x) + __bfloat162float(l0.x);
            o.y = __bfloat162float(h0.y) + __bfloat162float(l0.y);
            o.z = __bfloat162float(h1.x) + __bfloat162float(l1.x);
            o.w = __bfloat162float(h1.y) + __bfloat162float(l1.y);
            *(float4*)(probs + pb + (size_t)r * RDIM + s2 * 4) = o;
        }
    }

    float acc2[8][4];
    #pragma unroll
    for (int nt = 0; nt < 8; nt++)
        #pragma unroll
        for (int u = 0; u < 4; u++) acc2[nt][u] = 0.f;

    #pragma unroll
    for (int j16 = 0; j16 < 8; j16++) {
        uint32_t ph4[4], pl4[4];
        {
            int rr = i0 + (lane & 15);
            int cc = 2 * j16 + (lane >> 4);
            uint32_t ad = sb + AT_PHI + pswz(rr, cc);
            ldsm4(ph4, ad);
            ldsm4(pl4, ad + 32768);
        }
        #pragma unroll
        for (int dg = 0; dg < 4; dg++) {
            int jr = j16 * 16 + (lane & 7) + ((lane >> 3) & 1) * 8;
            int cc = 2 * dg + (lane >> 4);
            uint32_t vd = sb + AT_VHI + qswz(jr, cc);
            uint32_t vh4[4], vl4[4];
            ldsm4t(vh4, vd);
            ldsm4t(vl4, vd + 16384);
            mma16816(acc2[2 * dg], ph4, vh4[0], vh4[1]);
            mma16816(acc2[2 * dg], ph4, vl4[0], vl4[1]);
            mma16816(acc2[2 * dg], pl4, vh4[0], vh4[1]);
            mma16816(acc2[2 * dg + 1], ph4, vh4[2], vh4[3]);
            mma16816(acc2[2 * dg + 1], ph4, vl4[2], vl4[3]);
            mma16816(acc2[2 * dg + 1], pl4, vh4[2], vh4[3]);
        }
    }

    {
        const int r0 = i0 + (lane >> 2);
        #pragma unroll
        for (int nt = 0; nt < 8; nt++) {
            int d0 = nt * 8 + (lane & 3) * 2;
            size_t g0 = (size_t)r0 * (CDIM * EMBED) + base + d0;
            size_t g1 = (size_t)(r0 + 8) * (CDIM * EMBED) + base + d0;
            *(float2*)(ctx + g0) = make_float2(rtf(acc2[nt][0]), rtf(acc2[nt][1]));
            *(float2*)(ctx + g1) = make_float2(rtf(acc2[nt][2]), rtf(acc2[nt][3]));
        }
    }
}

// ---------------------------------------------------------------------------
extern "C" void kernel_launch(void* const* d_in, const int* in_sizes, int n_in,
                              void* d_out, int out_size)
{
    const float* x  = (const float*)d_in[0];
    const unsigned char* mask = (const unsigned char*)d_in[1];
    const float* Wq = (const float*)d_in[2];
    const float* bq = (const float*)d_in[3];
    const float* Wk = (const float*)d_in[4];
    const float* bk = (const float*)d_in[5];
    const float* Wv = (const float*)d_in[6];
    const float* bv = (const float*)d_in[7];
    const float* Wo = (const float*)d_in[8];
    const float* bo = (const float*)d_in[9];
    float* out = (float*)d_out;

    bf16 *xhi, *xlo, *qhi, *qlo, *khi, *klo, *vhi, *vlo, *whi, *wlo;
    float *xtf, *wvtf, *wotf, *ctx;
    cudaGetSymbolAddress((void**)&xhi, g_xhi);
    cudaGetSymbolAddress((void**)&xlo, g_xlo);
    cudaGetSymbolAddress((void**)&xtf, g_xtf);
    cudaGetSymbolAddress((void**)&qhi, g_qhi);
    cudaGetSymbolAddress((void**)&qlo, g_qlo);
    cudaGetSymbolAddress((void**)&khi, g_khi);
    cudaGetSymbolAddress((void**)&klo, g_klo);
    cudaGetSymbolAddress((void**)&vhi, g_vhi);
    cudaGetSymbolAddress((void**)&vlo, g_vlo);
    cudaGetSymbolAddress((void**)&whi, g_whi);
    cudaGetSymbolAddress((void**)&wlo, g_wlo);
    cudaGetSymbolAddress((void**)&wvtf, g_wvtf);
    cudaGetSymbolAddress((void**)&wotf, g_wotf);
    cudaGetSymbolAddress((void**)&ctx, g_ctx);

    const long long out_elems = (long long)NTOK * EMBED;
    const long long probs_elems = (long long)HEADS * CDIM * RDIM * RDIM;
    int write_probs = ((long long)out_size >= out_elems + probs_elems) ? 1 : 0;
    float* probs = write_probs ? (out + out_elems) : nullptr;

    cudaFuncSetAttribute(mma_gemm_qkv, cudaFuncAttributeMaxDynamicSharedMemorySize, GSMEM);
    cudaFuncSetAttribute(mma_gemm_out, cudaFuncAttributeMaxDynamicSharedMemorySize, GSMEM);
    cudaFuncSetAttribute(attn_mma, cudaFuncAttributeMaxDynamicSharedMemorySize, AT_SMEM);

    const size_t WSZ = (size_t)EMBED * EMBED;
    const int xn4 = (int)(((size_t)NTOK * EMBED) / 4);
    const int wn4 = (int)(WSZ / 4);

    split_x_kernel<<<(xn4 + 255) / 256, 256>>>((const float4*)x, xhi, xlo,
                                               (float4*)xtf, xn4);
    {
        dim3 wgrid((wn4 + 255) / 256, 2);
        split_w_kernel<<<wgrid, 256>>>((const float4*)Wq, (const float4*)Wk,
                                       whi, wlo, wn4);
        round_w_kernel<<<wgrid, 256>>>((const float4*)Wv, (const float4*)Wo,
                                       (float4*)wvtf, (float4*)wotf, wn4);
    }

    dim3 qkvgrid(18, NTOK / 128);          // (18, 256): 12 bf16 + 6 tf32 CTAs per row
    mma_gemm_qkv<<<qkvgrid, 256, GSMEM>>>(xhi, xlo, whi, wlo, xtf, wvtf,
                                          bq, bk, bv,
                                          qhi, qlo, khi, klo, vhi, vlo);

    dim3 agrid(CDIM, HEADS);
    attn_mma<<<agrid, 256, AT_SMEM>>>(qhi, qlo, khi, klo, vhi, vlo,
                                      mask, probs, ctx, write_probs);

    dim3 ogrid(EMBED / 128, NTOK / 128);   // (6, 256)
    mma_gemm_out<<<ogrid, 256, GSMEM>>>(ctx, wotf, bo, out);
}

// round 17
// speedup vs baseline: 1.6037x; 1.1666x over previous
#include <cuda_runtime.h>
#include <cuda_bf16.h>
#include <cstdint>

#define EMBED 768
#define HEADS 12
#define DKK   64
#define RDIM  128
#define CDIM  256
#define NTOK  (RDIM * CDIM)   // 32768

typedef __nv_bfloat16 bf16;
typedef __nv_bfloat162 bf162;

__device__ float g_xtf[(size_t)NTOK * EMBED];       // x rounded to tf32
__device__ bf16 g_qhi[(size_t)NTOK * EMBED];
__device__ bf16 g_qlo[(size_t)NTOK * EMBED];
__device__ bf16 g_khi[(size_t)NTOK * EMBED];
__device__ bf16 g_klo[(size_t)NTOK * EMBED];
__device__ bf16 g_vhi[(size_t)NTOK * EMBED];
__device__ bf16 g_vlo[(size_t)NTOK * EMBED];
__device__ float g_wtf[4 * (size_t)EMBED * EMBED];  // Wq,Wk,Wv,Wo rounded to tf32
__device__ float g_ctx[(size_t)NTOK * EMBED];       // tf32-rounded context

__device__ __forceinline__ uint32_t smem_u32(const void* p) {
    uint32_t a;
    asm("{ .reg .u64 t; cvta.to.shared.u64 t, %1; cvt.u32.u64 %0, t; }"
        : "=r"(a) : "l"(p));
    return a;
}

__device__ __forceinline__ float rtf(float x) {
    uint32_t u;
    asm("cvt.rna.tf32.f32 %0, %1;" : "=r"(u) : "f"(x));
    return __uint_as_float(u);
}

__device__ __forceinline__ void ldsm4(uint32_t (&r)[4], uint32_t addr) {
    asm volatile("ldmatrix.sync.aligned.m8n8.x4.shared.b16 {%0,%1,%2,%3}, [%4];"
                 : "=r"(r[0]), "=r"(r[1]), "=r"(r[2]), "=r"(r[3]) : "r"(addr));
}

__device__ __forceinline__ void ldsm4t(uint32_t (&r)[4], uint32_t addr) {
    asm volatile("ldmatrix.sync.aligned.m8n8.x4.trans.shared.b16 {%0,%1,%2,%3}, [%4];"
                 : "=r"(r[0]), "=r"(r[1]), "=r"(r[2]), "=r"(r[3]) : "r"(addr));
}

__device__ __forceinline__ void mma16816(float (&c)[4], const uint32_t (&a)[4],
                                         uint32_t b0, uint32_t b1) {
    asm volatile(
        "mma.sync.aligned.m16n8k16.row.col.f32.bf16.bf16.f32 "
        "{%0,%1,%2,%3}, {%4,%5,%6,%7}, {%8,%9}, {%0,%1,%2,%3};"
        : "+f"(c[0]), "+f"(c[1]), "+f"(c[2]), "+f"(c[3])
        : "r"(a[0]), "r"(a[1]), "r"(a[2]), "r"(a[3]), "r"(b0), "r"(b1));
}

__device__ __forceinline__ void mma_tf32(float (&c)[4], const uint32_t (&a)[4],
                                         uint32_t b0, uint32_t b1) {
    asm volatile(
        "mma.sync.aligned.m16n8k8.row.col.f32.tf32.tf32.f32 "
        "{%0,%1,%2,%3}, {%4,%5,%6,%7}, {%8,%9}, {%0,%1,%2,%3};"
        : "+f"(c[0]), "+f"(c[1]), "+f"(c[2]), "+f"(c[3])
        : "r"(a[0]), "r"(a[1]), "r"(a[2]), "r"(a[3]), "r"(b0), "r"(b1));
}

#define CP_ASYNC16(dst, src) \
    asm volatile("cp.async.cg.shared.global [%0], [%1], 16;" \
                 :: "r"(dst), "l"(src))
#define CP_COMMIT() asm volatile("cp.async.commit_group;" ::: "memory")
#define CP_WAIT0()  asm volatile("cp.async.wait_group 0;" ::: "memory")
#define CP_WAIT1()  asm volatile("cp.async.wait_group 1;" ::: "memory")

// ---------------------------------------------------------------------------
// x -> rounded-tf32 copy
__global__ __launch_bounds__(256) void round_x_kernel(
    const float4* __restrict__ src, float4* __restrict__ tf, int n4)
{
    int i = blockIdx.x * blockDim.x + threadIdx.x;
    if (i >= n4) return;
    float4 v = src[i];
    tf[i] = make_float4(rtf(v.x), rtf(v.y), rtf(v.z), rtf(v.w));
}

// Wq,Wk,Wv,Wo -> rounded tf32 (blockIdx.y selects weight)
__global__ __launch_bounds__(256) void round_w_kernel(
    const float4* __restrict__ w0, const float4* __restrict__ w1,
    const float4* __restrict__ w2, const float4* __restrict__ w3,
    float4* __restrict__ dst, int n4)
{
    int i = blockIdx.x * blockDim.x + threadIdx.x;
    if (i >= n4) return;
    const float4* src = (blockIdx.y == 0) ? w0 : (blockIdx.y == 1) ? w1 :
                        (blockIdx.y == 2) ? w2 : w3;
    float4 v = src[i];
    dst[(size_t)blockIdx.y * n4 + i] =
        make_float4(rtf(v.x), rtf(v.y), rtf(v.z), rtf(v.w));
}

// ---------------------------------------------------------------------------
// tf32 GEMM mainloop: CTA 128x128, 8 warps, K-chunk 32 (4 k8 steps), 128B
// swizzled rows, 3-stage cp.async pipeline (32KB/stage -> 96KB, 2 CTAs/SM).
// Operands pre-rounded to tf32 -> hardware truncation is exact.
// ---------------------------------------------------------------------------
#define KC      32
#define NCH     (EMBED / KC)          // 24
#define TILE32  16384
#define STAGE32 32768
#define GSMEM   (3 * STAGE32)         // 98304

__device__ __forceinline__ uint32_t cswz(int r, int c) {
    return (uint32_t)(r * 128 + ((c ^ (r & 7)) << 4));
}

__device__ __forceinline__ void gemm_mainloop_tf32(
    const float* __restrict__ A, const float* __restrict__ B,
    int row0, int col0, uint32_t sbase, float (&acc)[4][4][4])
{
    const int tid  = threadIdx.x;
    const int wid  = tid >> 5;
    const int lane = tid & 31;
    const int wm   = wid >> 2;
    const int wn   = wid & 3;

    const int arl = lane & 15;
    const int acl = lane >> 4;
    const int brl = ((lane & 16) >> 1) + (lane & 7);
    const int bcl = (lane >> 3) & 1;

    auto load_stage = [&](int s, int c) {
        uint32_t stage = sbase + s * STAGE32;
        #pragma unroll
        for (int it = 0; it < 8; it++) {
            int u = tid + it * 256;
            int t = u >> 10;
            int rem = u & 1023;
            int r = rem >> 3;
            int g = rem & 7;
            const float* src = t ? B : A;
            int grow = (t ? col0 : row0) + r;
            CP_ASYNC16(stage + (uint32_t)(t * TILE32) + cswz(r, g),
                       src + (size_t)grow * EMBED + c * KC + g * 4);
        }
    };

    load_stage(0, 0);
    CP_COMMIT();
    load_stage(1, 1);
    CP_COMMIT();

    int s = 0;
    for (int c = 0; c < NCH; c++) {
        if (c == NCH - 1) { CP_WAIT0(); } else { CP_WAIT1(); }
        __syncthreads();
        if (c + 2 < NCH) {
            int ns = s + 2;
            if (ns >= 3) ns -= 3;
            load_stage(ns, c + 2);
        }
        CP_COMMIT();

        const uint32_t st = sbase + s * STAGE32;
        #pragma unroll
        for (int kg = 0; kg < 4; kg++) {
            uint32_t av[4][4];
            #pragma unroll
            for (int mt = 0; mt < 4; mt++)
                ldsm4(av[mt], st + cswz(wm * 64 + mt * 16 + arl, 2 * kg + acl));
            #pragma unroll
            for (int np = 0; np < 2; np++) {
                uint32_t r4[4];
                ldsm4(r4, st + TILE32 +
                          cswz(wn * 32 + np * 16 + brl, 2 * kg + bcl));
                #pragma unroll
                for (int mt = 0; mt < 4; mt++) {
                    mma_tf32(acc[mt][2 * np], av[mt], r4[0], r4[1]);
                    mma_tf32(acc[mt][2 * np + 1], av[mt], r4[2], r4[3]);
                }
            }
        }
        s = (s == 2) ? 0 : s + 1;
    }
}

// Fused QKV GEMM, all tf32. grid (18, 256): wsel = x/6 (0=Q,1=K,2=V).
// Epilogue splits results to bf16 hi/lo for the attention kernel.
__global__ __launch_bounds__(256) void mma_gemm_qkv(
    const float* __restrict__ Xtf, const float* __restrict__ Wtf,
    const float* __restrict__ bq, const float* __restrict__ bk,
    const float* __restrict__ bv,
    bf16* __restrict__ qhi, bf16* __restrict__ qlo,
    bf16* __restrict__ khi, bf16* __restrict__ klo,
    bf16* __restrict__ vhi, bf16* __restrict__ vlo)
{
    extern __shared__ char smem[];
    const uint32_t sbase = smem_u32(smem);
    const int wsel = blockIdx.x / 6;
    const int col0 = (blockIdx.x % 6) * 128;
    const int row0 = blockIdx.y * 128;
    const size_t WSZ = (size_t)EMBED * EMBED;

    const float* bias = (wsel == 0) ? bq : (wsel == 1) ? bk : bv;
    bf16* Yhi = (wsel == 0) ? qhi : (wsel == 1) ? khi : vhi;
    bf16* Ylo = (wsel == 0) ? qlo : (wsel == 1) ? klo : vlo;
    const float scale = (wsel == 0) ? 0.125f : 1.f;

    float acc[4][4][4];
    #pragma unroll
    for (int mt = 0; mt < 4; mt++)
        #pragma unroll
        for (int nt = 0; nt < 4; nt++)
            #pragma unroll
            for (int u = 0; u < 4; u++) acc[mt][nt][u] = 0.f;

    gemm_mainloop_tf32(Xtf, Wtf + (size_t)wsel * WSZ, row0, col0, sbase, acc);

    const int lane = threadIdx.x & 31;
    const int wid  = threadIdx.x >> 5;
    const int wm   = wid >> 2;
    const int wn   = wid & 3;

    #pragma unroll
    for (int mt = 0; mt < 4; mt++) {
        int r0 = row0 + wm * 64 + mt * 16 + (lane >> 2);
        #pragma unroll
        for (int nt = 0; nt < 4; nt++) {
            int mcol = col0 + wn * 32 + nt * 8 + 2 * (lane & 3);
            float b0 = bias[mcol], b1 = bias[mcol + 1];
            float o0 = (acc[mt][nt][0] + b0) * scale;
            float o1 = (acc[mt][nt][1] + b1) * scale;
            float o2 = (acc[mt][nt][2] + b0) * scale;
            float o3 = (acc[mt][nt][3] + b1) * scale;
            bf16 h0 = __float2bfloat16(o0), h1 = __float2bfloat16(o1);
            bf16 h2 = __float2bfloat16(o2), h3 = __float2bfloat16(o3);
            *(bf162*)(Yhi + (size_t)r0 * EMBED + mcol) = bf162(h0, h1);
            *(bf162*)(Yhi + (size_t)(r0 + 8) * EMBED + mcol) = bf162(h2, h3);
            bf16 l0 = __float2bfloat16(o0 - __bfloat162float(h0));
            bf16 l1 = __float2bfloat16(o1 - __bfloat162float(h1));
            bf16 l2 = __float2bfloat16(o2 - __bfloat162float(h2));
            bf16 l3 = __float2bfloat16(o3 - __bfloat162float(h3));
            *(bf162*)(Ylo + (size_t)r0 * EMBED + mcol) = bf162(l0, l1);
            *(bf162*)(Ylo + (size_t)(r0 + 8) * EMBED + mcol) = bf162(l2, l3);
        }
    }
}

// Output-projection GEMM (tf32): grid (6, 256), f32 out.
__global__ __launch_bounds__(256) void mma_gemm_out(
    const float* __restrict__ Actx, const float* __restrict__ Bw,
    const float* __restrict__ bias, float* __restrict__ Yf)
{
    extern __shared__ char smem[];
    const uint32_t sbase = smem_u32(smem);
    const int col0 = blockIdx.x * 128;
    const int row0 = blockIdx.y * 128;

    const int lane = threadIdx.x & 31;
    const int wid  = threadIdx.x >> 5;
    const int wm   = wid >> 2;
    const int wn   = wid & 3;

    float acc[4][4][4];
    #pragma unroll
    for (int mt = 0; mt < 4; mt++)
        #pragma unroll
        for (int nt = 0; nt < 4; nt++)
            #pragma unroll
            for (int u = 0; u < 4; u++) acc[mt][nt][u] = 0.f;

    gemm_mainloop_tf32(Actx, Bw, row0, col0, sbase, acc);

    #pragma unroll
    for (int mt = 0; mt < 4; mt++) {
        int r0 = row0 + wm * 64 + mt * 16 + (lane >> 2);
        #pragma unroll
        for (int nt = 0; nt < 4; nt++) {
            int mcol = col0 + wn * 32 + nt * 8 + 2 * (lane & 3);
            float b0 = bias[mcol], b1 = bias[mcol + 1];
            *(float2*)(Yf + (size_t)r0 * EMBED + mcol) =
                make_float2(acc[mt][nt][0] + b0, acc[mt][nt][1] + b1);
            *(float2*)(Yf + (size_t)(r0 + 8) * EMBED + mcol) =
                make_float2(acc[mt][nt][2] + b0, acc[mt][nt][3] + b1);
        }
    }
}

// ---------------------------------------------------------------------------
// Attention via mma.sync (96KB smem, 2 CTAs/SM). Unchanged from R16.
// ---------------------------------------------------------------------------
#define AT_QHI 0
#define AT_QLO 16384
#define AT_KHI 32768
#define AT_KLO 49152
#define AT_VHI 65536
#define AT_VLO 81920
#define AT_PHI 0
#define AT_PLO 32768
#define AT_MKW 98304
#define AT_SMEM (98304 + 32)

__device__ __forceinline__ uint32_t qswz(int r, int c) {
    return (uint32_t)(r * 128 + ((c ^ (r & 7)) * 16));
}
__device__ __forceinline__ uint32_t pswz(int r, int c) {
    return (uint32_t)(r * 256 + (((c & 8) | ((c & 7) ^ (r & 7))) * 16));
}

__global__ __launch_bounds__(256) void attn_mma(
    const bf16* __restrict__ qhi, const bf16* __restrict__ qlo,
    const bf16* __restrict__ khi, const bf16* __restrict__ klo,
    const bf16* __restrict__ vhi, const bf16* __restrict__ vlo,
    const unsigned char* __restrict__ mask, float* __restrict__ probs,
    float* __restrict__ ctx, int write_probs)
{
    extern __shared__ char smc[];
    const uint32_t sb = smem_u32(smc);

    const int c = blockIdx.x;
    const int h = blockIdx.y;
    const int tid = threadIdx.x;
    const int wid = tid >> 5;
    const int lane = tid & 31;
    const size_t base = (size_t)c * EMBED + h * DKK;

    {
        const bf16* srcs[6] = { qhi, qlo, khi, klo, vhi, vlo };
        #pragma unroll
        for (int t = 0; t < 6; t++) {
            #pragma unroll
            for (int it = 0; it < 4; it++) {
                int e = tid + it * 256;
                int r = e >> 3;
                int ch = e & 7;
                CP_ASYNC16(sb + (uint32_t)(t * 16384) + qswz(r, ch),
                           srcs[t] + (size_t)r * (CDIM * EMBED) + base + ch * 8);
            }
        }
        CP_COMMIT();
    }
    if (tid < 4) {
        uint32_t w = 0;
        for (int b = 0; b < 32; b++)
            if (mask[(size_t)(tid * 32 + b) * CDIM + c]) w |= (1u << b);
        *(uint32_t*)(smc + AT_MKW + tid * 4) = w;
    }
    CP_WAIT0();
    __syncthreads();

    const int i0 = wid * 16;

    float acc[16][4];
    #pragma unroll
    for (int nt = 0; nt < 16; nt++)
        #pragma unroll
        for (int u = 0; u < 4; u++) acc[nt][u] = 0.f;

    #pragma unroll
    for (int ks = 0; ks < 4; ks++) {
        uint32_t ah[4], al[4];
        {
            int rr = i0 + (lane & 15);
            int cc = 2 * ks + (lane >> 4);
            uint32_t ad = sb + AT_QHI + qswz(rr, cc);
            ldsm4(ah, ad);
            ldsm4(al, ad + 16384);
        }
        #pragma unroll
        for (int jg = 0; jg < 8; jg++) {
            int jr = jg * 16 + ((lane & 16) >> 1) + (lane & 7);
            int cc = 2 * ks + ((lane >> 3) & 1);
            uint32_t bd = sb + AT_KHI + qswz(jr, cc);
            uint32_t bh[4], bl[4];
            ldsm4(bh, bd);
            ldsm4(bl, bd + 16384);
            mma16816(acc[2 * jg], ah, bh[0], bh[1]);
            mma16816(acc[2 * jg], ah, bl[0], bl[1]);
            mma16816(acc[2 * jg], al, bh[0], bh[1]);
            mma16816(acc[2 * jg + 1], ah, bh[2], bh[3]);
            mma16816(acc[2 * jg + 1], ah, bl[2], bl[3]);
            mma16816(acc[2 * jg + 1], al, bh[2], bh[3]);
        }
    }

    __syncthreads();

    {
        uint32_t mw[4];
        #pragma unroll
        for (int u = 0; u < 4; u++) mw[u] = *(const uint32_t*)(smc + AT_MKW + u * 4);
        const int jb = (lane & 3) * 2;

        float mxl = -1e30f, mxh = -1e30f;
        #pragma unroll
        for (int nt = 0; nt < 16; nt++) {
            int j0 = nt * 8 + jb;
            bool m0 = (mw[j0 >> 5] >> (j0 & 31)) & 1;
            bool m1 = (mw[j0 >> 5] >> ((j0 + 1) & 31)) & 1;
            if (m0) { acc[nt][0] = -10000.f; acc[nt][2] = -10000.f; }
            if (m1) { acc[nt][1] = -10000.f; acc[nt][3] = -10000.f; }
            mxl = fmaxf(mxl, fmaxf(acc[nt][0], acc[nt][1]));
            mxh = fmaxf(mxh, fmaxf(acc[nt][2], acc[nt][3]));
        }
        #pragma unroll
        for (int o = 1; o <= 2; o <<= 1) {
            mxl = fmaxf(mxl, __shfl_xor_sync(0xffffffffu, mxl, o));
            mxh = fmaxf(mxh, __shfl_xor_sync(0xffffffffu, mxh, o));
        }
        float sl = 0.f, sh = 0.f;
        #pragma unroll
        for (int nt = 0; nt < 16; nt++) {
            acc[nt][0] = __expf(acc[nt][0] - mxl);
            acc[nt][1] = __expf(acc[nt][1] - mxl);
            acc[nt][2] = __expf(acc[nt][2] - mxh);
            acc[nt][3] = __expf(acc[nt][3] - mxh);
            sl += acc[nt][0] + acc[nt][1];
            sh += acc[nt][2] + acc[nt][3];
        }
        #pragma unroll
        for (int o = 1; o <= 2; o <<= 1) {
            sl += __shfl_xor_sync(0xffffffffu, sl, o);
            sh += __shfl_xor_sync(0xffffffffu, sh, o);
        }
        float il = 1.f / sl, ih = 1.f / sh;

        const int rl = i0 + (lane >> 2);
        #pragma unroll
        for (int nt = 0; nt < 16; nt++) {
            float p0 = acc[nt][0] * il;
            float p1 = acc[nt][1] * il;
            float p2 = acc[nt][2] * ih;
            float p3 = acc[nt][3] * ih;
            bf16 h0 = __float2bfloat16(p0), h1 = __float2bfloat16(p1);
            bf16 h2 = __float2bfloat16(p2), h3 = __float2bfloat16(p3);
            uint32_t a0 = pswz(rl, nt) + (uint32_t)(jb * 2);
            uint32_t a1 = pswz(rl + 8, nt) + (uint32_t)(jb * 2);
            *(bf162*)(smc + AT_PHI + a0) = bf162(h0, h1);
            *(bf162*)(smc + AT_PHI + a1) = bf162(h2, h3);
            bf16 l0 = __float2bfloat16(p0 - __bfloat162float(h0));
            bf16 l1 = __float2bfloat16(p1 - __bfloat162float(h1));
            bf16 l2 = __float2bfloat16(p2 - __bfloat162float(h2));
            bf16 l3 = __float2bfloat16(p3 - __bfloat162float(h3));
            *(bf162*)(smc + AT_PLO + a0) = bf162(l0, l1);
            *(bf162*)(smc + AT_PLO + a1) = bf162(l2, l3);
        }
    }
    __syncthreads();

    if (write_probs) {
        const size_t pb = ((size_t)(h * CDIM + c) * RDIM) * RDIM;
        #pragma unroll
        for (int it = 0; it < 16; it++) {
            int e = tid + it * 256;
            int r = e >> 5;
            int s2 = e & 31;
            uint32_t pa = pswz(r, s2 >> 1) + (uint32_t)((s2 & 1) * 8);
            uint2 uh = *(const uint2*)(smc + AT_PHI + pa);
            uint2 ul = *(const uint2*)(smc + AT_PLO + pa);
            bf162 h0 = *(bf162*)&uh.x, h1 = *(bf162*)&uh.y;
            bf162 l0 = *(bf162*)&ul.x, l1 = *(bf162*)&ul.y;
            float4 o;
            o.x = __bfloat162float(h0.x) + __bfloat162float(l0.x);
            o.y = __bfloat162float(h0.y) + __bfloat162float(l0.y);
            o.z = __bfloat162float(h1.x) + __bfloat162float(l1.x);
            o.w = __bfloat162float(h1.y) + __bfloat162float(l1.y);
            *(float4*)(probs + pb + (size_t)r * RDIM + s2 * 4) = o;
        }
    }

    float acc2[8][4];
    #pragma unroll
    for (int nt = 0; nt < 8; nt++)
        #pragma unroll
        for (int u = 0; u < 4; u++) acc2[nt][u] = 0.f;

    #pragma unroll
    for (int j16 = 0; j16 < 8; j16++) {
        uint32_t ph4[4], pl4[4];
        {
            int rr = i0 + (lane & 15);
            int cc = 2 * j16 + (lane >> 4);
            uint32_t ad = sb + AT_PHI + pswz(rr, cc);
            ldsm4(ph4, ad);
            ldsm4(pl4, ad + 32768);
        }
        #pragma unroll
        for (int dg = 0; dg < 4; dg++) {
            int jr = j16 * 16 + (lane & 7) + ((lane >> 3) & 1) * 8;
            int cc = 2 * dg + (lane >> 4);
            uint32_t vd = sb + AT_VHI + qswz(jr, cc);
            uint32_t vh4[4], vl4[4];
            ldsm4t(vh4, vd);
            ldsm4t(vl4, vd + 16384);
            mma16816(acc2[2 * dg], ph4, vh4[0], vh4[1]);
            mma16816(acc2[2 * dg], ph4, vl4[0], vl4[1]);
            mma16816(acc2[2 * dg], pl4, vh4[0], vh4[1]);
            mma16816(acc2[2 * dg + 1], ph4, vh4[2], vh4[3]);
            mma16816(acc2[2 * dg + 1], ph4, vl4[2], vl4[3]);
            mma16816(acc2[2 * dg + 1], pl4, vh4[2], vh4[3]);
        }
    }

    {
        const int r0 = i0 + (lane >> 2);
        #pragma unroll
        for (int nt = 0; nt < 8; nt++) {
            int d0 = nt * 8 + (lane & 3) * 2;
            size_t g0 = (size_t)r0 * (CDIM * EMBED) + base + d0;
            size_t g1 = (size_t)(r0 + 8) * (CDIM * EMBED) + base + d0;
            *(float2*)(ctx + g0) = make_float2(rtf(acc2[nt][0]), rtf(acc2[nt][1]));
            *(float2*)(ctx + g1) = make_float2(rtf(acc2[nt][2]), rtf(acc2[nt][3]));
        }
    }
}

// ---------------------------------------------------------------------------
extern "C" void kernel_launch(void* const* d_in, const int* in_sizes, int n_in,
                              void* d_out, int out_size)
{
    const float* x  = (const float*)d_in[0];
    const unsigned char* mask = (const unsigned char*)d_in[1];
    const float* Wq = (const float*)d_in[2];
    const float* bq = (const float*)d_in[3];
    const float* Wk = (const float*)d_in[4];
    const float* bk = (const float*)d_in[5];
    const float* Wv = (const float*)d_in[6];
    const float* bv = (const float*)d_in[7];
    const float* Wo = (const float*)d_in[8];
    const float* bo = (const float*)d_in[9];
    float* out = (float*)d_out;

    bf16 *qhi, *qlo, *khi, *klo, *vhi, *vlo;
    float *xtf, *wtf, *ctx;
    cudaGetSymbolAddress((void**)&xtf, g_xtf);
    cudaGetSymbolAddress((void**)&qhi, g_qhi);
    cudaGetSymbolAddress((void**)&qlo, g_qlo);
    cudaGetSymbolAddress((void**)&khi, g_khi);
    cudaGetSymbolAddress((void**)&klo, g_klo);
    cudaGetSymbolAddress((void**)&vhi, g_vhi);
    cudaGetSymbolAddress((void**)&vlo, g_vlo);
    cudaGetSymbolAddress((void**)&wtf, g_wtf);
    cudaGetSymbolAddress((void**)&ctx, g_ctx);

    const long long out_elems = (long long)NTOK * EMBED;
    const long long probs_elems = (long long)HEADS * CDIM * RDIM * RDIM;
    int write_probs = ((long long)out_size >= out_elems + probs_elems) ? 1 : 0;
    float* probs = write_probs ? (out + out_elems) : nullptr;

    cudaFuncSetAttribute(mma_gemm_qkv, cudaFuncAttributeMaxDynamicSharedMemorySize, GSMEM);
    cudaFuncSetAttribute(mma_gemm_out, cudaFuncAttributeMaxDynamicSharedMemorySize, GSMEM);
    cudaFuncSetAttribute(attn_mma, cudaFuncAttributeMaxDynamicSharedMemorySize, AT_SMEM);

    const size_t WSZ = (size_t)EMBED * EMBED;
    const int xn4 = (int)(((size_t)NTOK * EMBED) / 4);
    const int wn4 = (int)(WSZ / 4);

    round_x_kernel<<<(xn4 + 255) / 256, 256>>>((const float4*)x, (float4*)xtf, xn4);
    {
        dim3 wgrid((wn4 + 255) / 256, 4);
        round_w_kernel<<<wgrid, 256>>>((const float4*)Wq, (const float4*)Wk,
                                       (const float4*)Wv, (const float4*)Wo,
                                       (float4*)wtf, wn4);
    }

    dim3 qkvgrid(18, NTOK / 128);          // (18, 256)
    mma_gemm_qkv<<<qkvgrid, 256, GSMEM>>>(xtf, wtf, bq, bk, bv,
                                          qhi, qlo, khi, klo, vhi, vlo);

    dim3 agrid(CDIM, HEADS);
    attn_mma<<<agrid, 256, AT_SMEM>>>(qhi, qlo, khi, klo, vhi, vlo,
                                      mask, probs, ctx, write_probs);

    dim3 ogrid(EMBED / 128, NTOK / 128);   // (6, 256)
    mma_gemm_out<<<ogrid, 256, GSMEM>>>(ctx, wtf + 3 * WSZ, bo, out);
}